// round 1
// baseline (speedup 1.0000x reference)
#include <cuda_runtime.h>
#include <cuda_bf16.h>
#include <cstddef>

// Problem constants
#define BB 4
#define TT 2048
#define CC 1024
#define HH 16
#define HD 64
// M = B*T = 8192 rows for all projections

// ---------------- scratch (static device globals; no allocation) ----------------
#define ELEMS (BB * TT * CC)  // 8,388,608
__device__ float g_Q[ELEMS];
__device__ float g_K[ELEMS];
__device__ float g_V[ELEMS];
__device__ float g_Y[ELEMS];

// ================================================================================
// GEMM: C[M,N] = A[M,K] @ W[N,K]^T (+ bias[N])
// BM=BN=128, BK=32, 256 threads, 8x8 micro-tile with strided (tx+16j / ty+16i)
// mapping for conflict-free smem reads.
// ================================================================================
#define BM 128
#define BN 128
#define BK 32
#define APAD 4  // smem row pad

__global__ __launch_bounds__(256) void gemm_bias_kernel(
    const float* __restrict__ A, const float* __restrict__ W,
    const float* __restrict__ bias, float* __restrict__ C,
    int M, int N, int K)
{
    __shared__ float As[BK][BM + APAD];
    __shared__ float Bs[BK][BN + APAD];

    const int tid = threadIdx.x;
    const int ty = tid >> 4;        // 0..15
    const int tx = tid & 15;        // 0..15
    const int bm = blockIdx.y * BM;
    const int bn = blockIdx.x * BN;

    float acc[8][8];
#pragma unroll
    for (int i = 0; i < 8; i++)
#pragma unroll
        for (int j = 0; j < 8; j++) acc[i][j] = 0.0f;

    for (int k0 = 0; k0 < K; k0 += BK) {
        // load A tile (BM x BK) transposed into smem: 1024 float4, 4 per thread
#pragma unroll
        for (int f = tid; f < BM * BK / 4; f += 256) {
            int row = f >> 3;              // BK/4 = 8 float4 per row
            int c4  = (f & 7) << 2;
            float4 v = *(const float4*)&A[(size_t)(bm + row) * K + k0 + c4];
            As[c4 + 0][row] = v.x;
            As[c4 + 1][row] = v.y;
            As[c4 + 2][row] = v.z;
            As[c4 + 3][row] = v.w;
        }
#pragma unroll
        for (int f = tid; f < BN * BK / 4; f += 256) {
            int row = f >> 3;
            int c4  = (f & 7) << 2;
            float4 v = *(const float4*)&W[(size_t)(bn + row) * K + k0 + c4];
            Bs[c4 + 0][row] = v.x;
            Bs[c4 + 1][row] = v.y;
            Bs[c4 + 2][row] = v.z;
            Bs[c4 + 3][row] = v.w;
        }
        __syncthreads();

#pragma unroll
        for (int k = 0; k < BK; k++) {
            float a[8], b[8];
#pragma unroll
            for (int i = 0; i < 8; i++) a[i] = As[k][ty + 16 * i];
#pragma unroll
            for (int j = 0; j < 8; j++) b[j] = Bs[k][tx + 16 * j];
#pragma unroll
            for (int i = 0; i < 8; i++)
#pragma unroll
                for (int j = 0; j < 8; j++)
                    acc[i][j] = fmaf(a[i], b[j], acc[i][j]);
        }
        __syncthreads();
    }

#pragma unroll
    for (int i = 0; i < 8; i++) {
        int r = bm + ty + 16 * i;
#pragma unroll
        for (int j = 0; j < 8; j++) {
            int c = bn + tx + 16 * j;
            float v = acc[i][j];
            if (bias) v += bias[c];
            C[(size_t)r * N + c] = v;
        }
    }
}

// ================================================================================
// Flash attention (causal), fp32. One block = one (q-tile 64 rows, b, h).
// 256 threads, 4x4 register micro-tiles for both S = Q K^T and O = P V.
// Online softmax with running (m, l); causal tile-skip: kv tiles 0..qt only.
// ================================================================================
#define AST 68  // smem row stride (64 + 4 pad) -> conflict-free & float4-aligned

__device__ __forceinline__ float rmax16(float v) {
#pragma unroll
    for (int off = 8; off; off >>= 1)
        v = fmaxf(v, __shfl_xor_sync(0xffffffffu, v, off));
    return v;
}
__device__ __forceinline__ float rsum16(float v) {
#pragma unroll
    for (int off = 8; off; off >>= 1)
        v += __shfl_xor_sync(0xffffffffu, v, off);
    return v;
}

__global__ __launch_bounds__(256) void attn_kernel(
    const float* __restrict__ Q, const float* __restrict__ K,
    const float* __restrict__ V, float* __restrict__ Y)
{
    extern __shared__ float sm[];
    float* Qs  = sm;                 // [64][AST]  row-major (r, d)
    float* Kts = sm + 64 * AST;      // [64][AST]  transposed (d, kvpos)
    float* Vs  = sm + 2 * 64 * AST;  // [64][AST]  row-major (kvpos, d)
    float* Ps  = sm + 3 * 64 * AST;  // [64][AST]  (r, kvpos)

    const int tid = threadIdx.x;
    const int ty = tid >> 4;   // 0..15
    const int tx = tid & 15;   // 0..15
    const int qt = blockIdx.x; // 0..31
    const int bh = blockIdx.y; // 0..63
    const int b = bh >> 4;
    const int h = bh & 15;
    const int q0 = qt * 64;
    const size_t base = ((size_t)b * TT) * CC + (size_t)h * HD;
    const float scale = 0.125f; // 1/sqrt(64)

    // load Q tile (scaled): 64x64 = 1024 float4, 4 per thread
#pragma unroll
    for (int f = tid; f < 1024; f += 256) {
        int row = f >> 4;
        int c4  = (f & 15) << 2;
        float4 v = *(const float4*)&Q[base + (size_t)(q0 + row) * CC + c4];
        float4 w = make_float4(v.x * scale, v.y * scale, v.z * scale, v.w * scale);
        *(float4*)&Qs[row * AST + c4] = w;
    }

    float m[4], l[4], o[4][4];
#pragma unroll
    for (int i = 0; i < 4; i++) {
        m[i] = -3.0e38f; l[i] = 0.0f;
#pragma unroll
        for (int j = 0; j < 4; j++) o[i][j] = 0.0f;
    }

    for (int kt = 0; kt <= qt; kt++) {
        __syncthreads(); // previous iter's reads of Kts/Vs/Ps done (also covers Qs, iter 0)
#pragma unroll
        for (int f = tid; f < 1024; f += 256) {
            int row = f >> 4;
            int c4  = (f & 15) << 2;
            size_t g = base + (size_t)(kt * 64 + row) * CC + c4;
            float4 kv = *(const float4*)&K[g];
            Kts[(c4 + 0) * AST + row] = kv.x;
            Kts[(c4 + 1) * AST + row] = kv.y;
            Kts[(c4 + 2) * AST + row] = kv.z;
            Kts[(c4 + 3) * AST + row] = kv.w;
            float4 vv = *(const float4*)&V[g];
            *(float4*)&Vs[row * AST + c4] = vv;
        }
        __syncthreads();

        // S = Qs @ Kts : thread covers rows ty+16i, cols tx+16j
        float s[4][4];
#pragma unroll
        for (int i = 0; i < 4; i++)
#pragma unroll
            for (int j = 0; j < 4; j++) s[i][j] = 0.0f;

#pragma unroll 8
        for (int d = 0; d < 64; d++) {
            float qv[4], kv[4];
#pragma unroll
            for (int i = 0; i < 4; i++) qv[i] = Qs[(ty + 16 * i) * AST + d];
#pragma unroll
            for (int j = 0; j < 4; j++) kv[j] = Kts[d * AST + tx + 16 * j];
#pragma unroll
            for (int i = 0; i < 4; i++)
#pragma unroll
                for (int j = 0; j < 4; j++)
                    s[i][j] = fmaf(qv[i], kv[j], s[i][j]);
        }

        if (kt == qt) { // diagonal tile: causal mask
#pragma unroll
            for (int i = 0; i < 4; i++)
#pragma unroll
                for (int j = 0; j < 4; j++)
                    if (tx + 16 * j > ty + 16 * i) s[i][j] = -3.0e38f;
        }

        // online softmax, write P to smem
#pragma unroll
        for (int i = 0; i < 4; i++) {
            float mt = fmaxf(fmaxf(s[i][0], s[i][1]), fmaxf(s[i][2], s[i][3]));
            mt = rmax16(mt);
            float mn = fmaxf(m[i], mt);
            float corr = __expf(m[i] - mn);
            float ps = 0.0f;
#pragma unroll
            for (int j = 0; j < 4; j++) {
                float p = __expf(s[i][j] - mn);
                ps += p;
                Ps[(ty + 16 * i) * AST + tx + 16 * j] = p;
            }
            ps = rsum16(ps);
            l[i] = l[i] * corr + ps;
            m[i] = mn;
#pragma unroll
            for (int j = 0; j < 4; j++) o[i][j] *= corr;
        }
        __syncthreads(); // all of Ps written

        // O += Ps @ Vs : thread covers rows ty+16i, head-dims tx+16j
#pragma unroll 8
        for (int k = 0; k < 64; k++) {
            float pv[4], vv[4];
#pragma unroll
            for (int i = 0; i < 4; i++) pv[i] = Ps[(ty + 16 * i) * AST + k];
#pragma unroll
            for (int j = 0; j < 4; j++) vv[j] = Vs[k * AST + tx + 16 * j];
#pragma unroll
            for (int i = 0; i < 4; i++)
#pragma unroll
                for (int j = 0; j < 4; j++)
                    o[i][j] = fmaf(pv[i], vv[j], o[i][j]);
        }
    }

    // normalize and store merged-head layout [B,T,C]
#pragma unroll
    for (int i = 0; i < 4; i++) {
        float inv = 1.0f / l[i];
        int r = q0 + ty + 16 * i;
#pragma unroll
        for (int j = 0; j < 4; j++) {
            Y[base + (size_t)r * CC + tx + 16 * j] = o[i][j] * inv;
        }
    }
}

// ================================================================================
// launch
// ================================================================================
extern "C" void kernel_launch(void* const* d_in, const int* in_sizes, int n_in,
                              void* d_out, int out_size)
{
    const float* x  = (const float*)d_in[0];
    const float* Wq = (const float*)d_in[1];
    const float* bq = (const float*)d_in[2];
    const float* Wk = (const float*)d_in[3];
    const float* bk = (const float*)d_in[4];
    const float* Wv = (const float*)d_in[5];
    const float* bv = (const float*)d_in[6];
    const float* Wp = (const float*)d_in[7];
    float* out = (float*)d_out;

    float *qp, *kp, *vp, *yp;
    cudaGetSymbolAddress((void**)&qp, g_Q);
    cudaGetSymbolAddress((void**)&kp, g_K);
    cudaGetSymbolAddress((void**)&vp, g_V);
    cudaGetSymbolAddress((void**)&yp, g_Y);

    const int M = BB * TT;             // 8192
    dim3 gg(CC / BN, M / BM);          // (8, 64)

    gemm_bias_kernel<<<gg, 256>>>(x, Wq, bq, qp, M, CC, CC);
    gemm_bias_kernel<<<gg, 256>>>(x, Wk, bk, kp, M, CC, CC);
    gemm_bias_kernel<<<gg, 256>>>(x, Wv, bv, vp, M, CC, CC);

    const int smem_attn = 4 * 64 * AST * (int)sizeof(float); // 69632 B
    cudaFuncSetAttribute(attn_kernel, cudaFuncAttributeMaxDynamicSharedMemorySize,
                         smem_attn);
    attn_kernel<<<dim3(TT / 64, BB * HH), 256, smem_attn>>>(qp, kp, vp, yp);

    gemm_bias_kernel<<<gg, 256>>>(yp, Wp, nullptr, out, M, CC, CC);
}

// round 3
// speedup vs baseline: 1.6539x; 1.6539x over previous
#include <cuda_runtime.h>
#include <cuda_bf16.h>
#include <cstdint>
#include <cstddef>

// Problem constants
#define BB 4
#define TT 2048
#define CC 1024
#define HH 16
#define HD 64
#define MM (BB * TT)          // 8192 rows

// ---------------- scratch (static device globals; no allocation) ----------------
#define ELEMS (BB * TT * CC)  // 8,388,608
__device__ float g_Q[ELEMS];
__device__ float g_K[ELEMS];
__device__ float g_V[ELEMS];
__device__ float g_Y[ELEMS];
__device__ __nv_bfloat16 g_xh[ELEMS];
__device__ __nv_bfloat16 g_xl[ELEMS];
__device__ __nv_bfloat16 g_yh[ELEMS];
__device__ __nv_bfloat16 g_yl[ELEMS];
__device__ __nv_bfloat16 g_wh[4 * CC * CC];
__device__ __nv_bfloat16 g_wl[4 * CC * CC];

// ================================================================================
// PTX helpers (base sm_103-safe: mma.sync / ldmatrix / cp.async only)
// ================================================================================
__device__ __forceinline__ uint32_t smem_u32(const void* p) {
    uint32_t a;
    asm("{ .reg .u64 t; cvta.to.shared.u64 t, %1; cvt.u32.u64 %0, t; }" : "=r"(a) : "l"(p));
    return a;
}

__device__ __forceinline__ void cp16(uint32_t dst, const void* src) {
    asm volatile("cp.async.cg.shared.global [%0], [%1], 16;" :: "r"(dst), "l"(src));
}
#define CP_COMMIT() asm volatile("cp.async.commit_group;" ::: "memory")
#define CP_WAIT(n)  asm volatile("cp.async.wait_group %0;" :: "n"(n) : "memory")

__device__ __forceinline__ void ldm_x4(uint32_t* r, uint32_t addr) {
    asm volatile("ldmatrix.sync.aligned.m8n8.x4.shared.b16 {%0,%1,%2,%3}, [%4];"
        : "=r"(r[0]), "=r"(r[1]), "=r"(r[2]), "=r"(r[3]) : "r"(addr));
}

__device__ __forceinline__ void mma_bf16(float* d, const uint32_t* a,
                                         uint32_t b0, uint32_t b1) {
    asm volatile(
        "mma.sync.aligned.m16n8k16.row.col.f32.bf16.bf16.f32 "
        "{%0,%1,%2,%3}, {%4,%5,%6,%7}, {%8,%9}, {%0,%1,%2,%3};"
        : "+f"(d[0]), "+f"(d[1]), "+f"(d[2]), "+f"(d[3])
        : "r"(a[0]), "r"(a[1]), "r"(a[2]), "r"(a[3]), "r"(b0), "r"(b1));
}

// SW128 swizzle on a 128B-row tile: bits[4:6] ^= row&7
#define SWZ(row, kbyte) (((row) << 7) + ((kbyte) ^ (((row) & 7) << 4)))

// ================================================================================
// split fp32 -> bf16 hi + bf16 lo
// ================================================================================
__global__ __launch_bounds__(256) void split_kernel(
    const float* __restrict__ src, __nv_bfloat16* __restrict__ hi,
    __nv_bfloat16* __restrict__ lo, int n4)
{
    int i = blockIdx.x * 256 + threadIdx.x;
    if (i >= n4) return;
    float4 v = ((const float4*)src)[i];
    __nv_bfloat16 h0 = __float2bfloat16(v.x);
    __nv_bfloat16 h1 = __float2bfloat16(v.y);
    __nv_bfloat16 h2 = __float2bfloat16(v.z);
    __nv_bfloat16 h3 = __float2bfloat16(v.w);
    __nv_bfloat16 l0 = __float2bfloat16(v.x - __bfloat162float(h0));
    __nv_bfloat16 l1 = __float2bfloat16(v.y - __bfloat162float(h1));
    __nv_bfloat16 l2 = __float2bfloat16(v.z - __bfloat162float(h2));
    __nv_bfloat16 l3 = __float2bfloat16(v.w - __bfloat162float(h3));
    ((__nv_bfloat162*)hi)[2 * i + 0] = __nv_bfloat162(h0, h1);
    ((__nv_bfloat162*)hi)[2 * i + 1] = __nv_bfloat162(h2, h3);
    ((__nv_bfloat162*)lo)[2 * i + 0] = __nv_bfloat162(l0, l1);
    ((__nv_bfloat162*)lo)[2 * i + 1] = __nv_bfloat162(l2, l3);
}

// ================================================================================
// bf16x3 mma.sync GEMM: C[M,N] = A[M,K] @ W[N,K]^T (+bias), fp32 out
// 128x128 tile/CTA, 8 warps (2m x 4n), warp tile 64x32, K-chunk 64,
// cp.async double-buffered SW128 smem, ldmatrix operand loads.
// ================================================================================
#define KC 64
#define NCHUNK (CC / KC)      // 16
#define TILE_B 16384          // 128 rows x 128B (64 bf16)
#define BUF_B (4 * TILE_B)    // AH, AL, BH, BL
#define SMEM_GEMM (2 * BUF_B) // 131072

__global__ __launch_bounds__(256) void gemm_mma_kernel(
    const __nv_bfloat16* __restrict__ Ah, const __nv_bfloat16* __restrict__ Al,
    const __nv_bfloat16* __restrict__ Bh, const __nv_bfloat16* __restrict__ Bl,
    const float* __restrict__ bias, float* __restrict__ C)
{
    extern __shared__ char smem[];
    const uint32_t sbase = smem_u32(smem);
    const int tid = threadIdx.x;
    const int wid = tid >> 5;
    const int lane = tid & 31;
    const int wm = wid & 1;        // 0..1 -> rows wm*64
    const int wn = wid >> 1;       // 0..3 -> cols wn*32
    const int bm = blockIdx.y * 128;
    const int bn = blockIdx.x * 128;

    const __nv_bfloat16* srcs[4] = {Ah, Al, Bh, Bl};

    // ldmatrix per-lane addressing components
    const int li = lane & 7;            // row within 8x8 matrix
    const int lrow = li + ((lane >> 3) & 1) * 8;   // row within 16-row frag
    const int lkb = (lane >> 4) * 16;              // 16B k-half select

    float acc[4][4][4];
#pragma unroll
    for (int a = 0; a < 4; a++)
#pragma unroll
        for (int b = 0; b < 4; b++)
#pragma unroll
            for (int c = 0; c < 4; c++) acc[a][b][c] = 0.0f;

    // ---- async load of one K-chunk into buffer `buf` ----
    auto load_chunk = [&](int chunk, int buf) {
        const int k0 = chunk * KC;
        const uint32_t tbu = sbase + buf * BUF_B;
#pragma unroll
        for (int part = 0; part < 4; part++) {
            const __nv_bfloat16* p = srcs[part];
            const int roff = (part < 2) ? bm : bn;
            const uint32_t db = tbu + part * TILE_B;
#pragma unroll
            for (int f = tid; f < 1024; f += 256) {
                int row = f >> 3;
                int c16 = f & 7;
                cp16(db + SWZ(row, c16 * 16),
                     p + (size_t)(roff + row) * CC + k0 + c16 * 8);
            }
        }
        CP_COMMIT();
    };

    load_chunk(0, 0);

    for (int chunk = 0; chunk < NCHUNK; chunk++) {
        const int buf = chunk & 1;
        if (chunk + 1 < NCHUNK) {
            load_chunk(chunk + 1, buf ^ 1);
            CP_WAIT(1);
        } else {
            CP_WAIT(0);
        }
        __syncthreads();

        const uint32_t tAh = sbase + buf * BUF_B;
        const uint32_t tAl = tAh + TILE_B;
        const uint32_t tBh = tAh + 2 * TILE_B;
        const uint32_t tBl = tAh + 3 * TILE_B;

#pragma unroll
        for (int ks = 0; ks < 4; ks++) {      // 4 x k16 within the 64-chunk
            const int kb = ks * 32;           // byte base of this k16
            uint32_t ah[4][4], al[4][4], bh[2][4], bl[2][4];
#pragma unroll
            for (int mi = 0; mi < 4; mi++) {
                int row = wm * 64 + mi * 16 + lrow;
                uint32_t off = SWZ(row, kb + lkb);
                ldm_x4(ah[mi], tAh + off);
                ldm_x4(al[mi], tAl + off);
            }
#pragma unroll
            for (int nj2 = 0; nj2 < 2; nj2++) {
                int row = wn * 32 + nj2 * 16 + lrow;
                uint32_t off = SWZ(row, kb + lkb);
                ldm_x4(bh[nj2], tBh + off);
                ldm_x4(bl[nj2], tBl + off);
            }
#pragma unroll
            for (int mi = 0; mi < 4; mi++) {
#pragma unroll
                for (int nj = 0; nj < 4; nj++) {
                    const int h = nj & 1;
                    mma_bf16(acc[mi][nj], ah[mi], bh[nj >> 1][h], bh[nj >> 1][h + 2]);
                    mma_bf16(acc[mi][nj], ah[mi], bl[nj >> 1][h], bl[nj >> 1][h + 2]);
                    mma_bf16(acc[mi][nj], al[mi], bh[nj >> 1][h], bh[nj >> 1][h + 2]);
                }
            }
        }
        __syncthreads();
    }

    // ---- epilogue: direct stores (float2), optional bias ----
    const int lr = lane >> 2;          // row offset within frag
    const int lc = (lane & 3) * 2;     // col offset within n8
#pragma unroll
    for (int nj = 0; nj < 4; nj++) {
        const int c = bn + wn * 32 + nj * 8 + lc;
        float b0 = 0.0f, b1 = 0.0f;
        if (bias) { b0 = bias[c]; b1 = bias[c + 1]; }
#pragma unroll
        for (int mi = 0; mi < 4; mi++) {
            const int r = bm + wm * 64 + mi * 16 + lr;
            float2 v0 = make_float2(acc[mi][nj][0] + b0, acc[mi][nj][1] + b1);
            float2 v1 = make_float2(acc[mi][nj][2] + b0, acc[mi][nj][3] + b1);
            *(float2*)&C[(size_t)r * CC + c] = v0;
            *(float2*)&C[(size_t)(r + 8) * CC + c] = v1;
        }
    }
}

// ================================================================================
// Flash attention (causal), fp32 — unchanged (known-good)
// ================================================================================
#define AST 68

__device__ __forceinline__ float rmax16(float v) {
#pragma unroll
    for (int off = 8; off; off >>= 1)
        v = fmaxf(v, __shfl_xor_sync(0xffffffffu, v, off));
    return v;
}
__device__ __forceinline__ float rsum16(float v) {
#pragma unroll
    for (int off = 8; off; off >>= 1)
        v += __shfl_xor_sync(0xffffffffu, v, off);
    return v;
}

__global__ __launch_bounds__(256) void attn_kernel(
    const float* __restrict__ Q, const float* __restrict__ K,
    const float* __restrict__ V, float* __restrict__ Y)
{
    extern __shared__ float sm[];
    float* Qs  = sm;
    float* Kts = sm + 64 * AST;
    float* Vs  = sm + 2 * 64 * AST;
    float* Ps  = sm + 3 * 64 * AST;

    const int tid = threadIdx.x;
    const int ty = tid >> 4;
    const int tx = tid & 15;
    const int qt = blockIdx.x;
    const int bh = blockIdx.y;
    const int b = bh >> 4;
    const int h = bh & 15;
    const int q0 = qt * 64;
    const size_t base = ((size_t)b * TT) * CC + (size_t)h * HD;
    const float scale = 0.125f;

#pragma unroll
    for (int f = tid; f < 1024; f += 256) {
        int row = f >> 4;
        int c4  = (f & 15) << 2;
        float4 v = *(const float4*)&Q[base + (size_t)(q0 + row) * CC + c4];
        float4 w = make_float4(v.x * scale, v.y * scale, v.z * scale, v.w * scale);
        *(float4*)&Qs[row * AST + c4] = w;
    }

    float m[4], l[4], o[4][4];
#pragma unroll
    for (int i = 0; i < 4; i++) {
        m[i] = -3.0e38f; l[i] = 0.0f;
#pragma unroll
        for (int j = 0; j < 4; j++) o[i][j] = 0.0f;
    }

    for (int kt = 0; kt <= qt; kt++) {
        __syncthreads();
#pragma unroll
        for (int f = tid; f < 1024; f += 256) {
            int row = f >> 4;
            int c4  = (f & 15) << 2;
            size_t g = base + (size_t)(kt * 64 + row) * CC + c4;
            float4 kv = *(const float4*)&K[g];
            Kts[(c4 + 0) * AST + row] = kv.x;
            Kts[(c4 + 1) * AST + row] = kv.y;
            Kts[(c4 + 2) * AST + row] = kv.z;
            Kts[(c4 + 3) * AST + row] = kv.w;
            float4 vv = *(const float4*)&V[g];
            *(float4*)&Vs[row * AST + c4] = vv;
        }
        __syncthreads();

        float s[4][4];
#pragma unroll
        for (int i = 0; i < 4; i++)
#pragma unroll
            for (int j = 0; j < 4; j++) s[i][j] = 0.0f;

#pragma unroll 8
        for (int d = 0; d < 64; d++) {
            float qv[4], kv[4];
#pragma unroll
            for (int i = 0; i < 4; i++) qv[i] = Qs[(ty + 16 * i) * AST + d];
#pragma unroll
            for (int j = 0; j < 4; j++) kv[j] = Kts[d * AST + tx + 16 * j];
#pragma unroll
            for (int i = 0; i < 4; i++)
#pragma unroll
                for (int j = 0; j < 4; j++)
                    s[i][j] = fmaf(qv[i], kv[j], s[i][j]);
        }

        if (kt == qt) {
#pragma unroll
            for (int i = 0; i < 4; i++)
#pragma unroll
                for (int j = 0; j < 4; j++)
                    if (tx + 16 * j > ty + 16 * i) s[i][j] = -3.0e38f;
        }

#pragma unroll
        for (int i = 0; i < 4; i++) {
            float mt = fmaxf(fmaxf(s[i][0], s[i][1]), fmaxf(s[i][2], s[i][3]));
            mt = rmax16(mt);
            float mn = fmaxf(m[i], mt);
            float corr = __expf(m[i] - mn);
            float ps = 0.0f;
#pragma unroll
            for (int j = 0; j < 4; j++) {
                float p = __expf(s[i][j] - mn);
                ps += p;
                Ps[(ty + 16 * i) * AST + tx + 16 * j] = p;
            }
            ps = rsum16(ps);
            l[i] = l[i] * corr + ps;
            m[i] = mn;
#pragma unroll
            for (int j = 0; j < 4; j++) o[i][j] *= corr;
        }
        __syncthreads();

#pragma unroll 8
        for (int k = 0; k < 64; k++) {
            float pv[4], vv[4];
#pragma unroll
            for (int i = 0; i < 4; i++) pv[i] = Ps[(ty + 16 * i) * AST + k];
#pragma unroll
            for (int j = 0; j < 4; j++) vv[j] = Vs[k * AST + tx + 16 * j];
#pragma unroll
            for (int i = 0; i < 4; i++)
#pragma unroll
                for (int j = 0; j < 4; j++)
                    o[i][j] = fmaf(pv[i], vv[j], o[i][j]);
        }
    }

#pragma unroll
    for (int i = 0; i < 4; i++) {
        float inv = 1.0f / l[i];
        int r = q0 + ty + 16 * i;
#pragma unroll
        for (int j = 0; j < 4; j++) {
            Y[base + (size_t)r * CC + tx + 16 * j] = o[i][j] * inv;
        }
    }
}

// ================================================================================
// launch
// ================================================================================
extern "C" void kernel_launch(void* const* d_in, const int* in_sizes, int n_in,
                              void* d_out, int out_size)
{
    const float* x  = (const float*)d_in[0];
    const float* Wq = (const float*)d_in[1];
    const float* bq = (const float*)d_in[2];
    const float* Wk = (const float*)d_in[3];
    const float* bk = (const float*)d_in[4];
    const float* Wv = (const float*)d_in[5];
    const float* bv = (const float*)d_in[6];
    const float* Wp = (const float*)d_in[7];
    float* out = (float*)d_out;

    float *qp, *kp, *vp, *yp;
    cudaGetSymbolAddress((void**)&qp, g_Q);
    cudaGetSymbolAddress((void**)&kp, g_K);
    cudaGetSymbolAddress((void**)&vp, g_V);
    cudaGetSymbolAddress((void**)&yp, g_Y);
    __nv_bfloat16 *xh, *xl, *yh, *yl, *wh, *wl;
    cudaGetSymbolAddress((void**)&xh, g_xh);
    cudaGetSymbolAddress((void**)&xl, g_xl);
    cudaGetSymbolAddress((void**)&yh, g_yh);
    cudaGetSymbolAddress((void**)&yl, g_yl);
    cudaGetSymbolAddress((void**)&wh, g_wh);
    cudaGetSymbolAddress((void**)&wl, g_wl);

    const int WSZ = CC * CC;

    cudaFuncSetAttribute(gemm_mma_kernel, cudaFuncAttributeMaxDynamicSharedMemorySize,
                         SMEM_GEMM);
    cudaFuncSetAttribute(attn_kernel, cudaFuncAttributeMaxDynamicSharedMemorySize,
                         4 * 64 * AST * (int)sizeof(float));

    // splits
    split_kernel<<<ELEMS / 4 / 256, 256>>>(x, xh, xl, ELEMS / 4);
    split_kernel<<<WSZ / 4 / 256, 256>>>(Wq, wh + 0 * WSZ, wl + 0 * WSZ, WSZ / 4);
    split_kernel<<<WSZ / 4 / 256, 256>>>(Wk, wh + 1 * WSZ, wl + 1 * WSZ, WSZ / 4);
    split_kernel<<<WSZ / 4 / 256, 256>>>(Wv, wh + 2 * WSZ, wl + 2 * WSZ, WSZ / 4);
    split_kernel<<<WSZ / 4 / 256, 256>>>(Wp, wh + 3 * WSZ, wl + 3 * WSZ, WSZ / 4);

    dim3 gg(CC / 128, MM / 128);  // (8, 64)
    gemm_mma_kernel<<<gg, 256, SMEM_GEMM>>>(xh, xl, wh + 0 * WSZ, wl + 0 * WSZ, bq, qp);
    gemm_mma_kernel<<<gg, 256, SMEM_GEMM>>>(xh, xl, wh + 1 * WSZ, wl + 1 * WSZ, bk, kp);
    gemm_mma_kernel<<<gg, 256, SMEM_GEMM>>>(xh, xl, wh + 2 * WSZ, wl + 2 * WSZ, bv, vp);

    // attention (fp32)
    const int smem_attn = 4 * 64 * AST * (int)sizeof(float);
    attn_kernel<<<dim3(TT / 64, BB * HH), 256, smem_attn>>>(qp, kp, vp, yp);

    // output projection
    split_kernel<<<ELEMS / 4 / 256, 256>>>(yp, yh, yl, ELEMS / 4);
    gemm_mma_kernel<<<gg, 256, SMEM_GEMM>>>(yh, yl, wh + 3 * WSZ, wl + 3 * WSZ, nullptr, out);
}

// round 4
// speedup vs baseline: 2.9528x; 1.7853x over previous
#include <cuda_runtime.h>
#include <cuda_bf16.h>
#include <cstdint>
#include <cstddef>

// Problem constants
#define BB 4
#define TT 2048
#define CC 1024
#define HH 16
#define HD 64
#define MM (BB * TT)          // 8192 rows

// ---------------- scratch (static device globals; no allocation) ----------------
#define ELEMS (BB * TT * CC)  // 8,388,608
__device__ __nv_bfloat16 g_xh[ELEMS];
__device__ __nv_bfloat16 g_xl[ELEMS];
__device__ __nv_bfloat16 g_qh[ELEMS];
__device__ __nv_bfloat16 g_ql[ELEMS];
__device__ __nv_bfloat16 g_kh[ELEMS];
__device__ __nv_bfloat16 g_kl[ELEMS];
__device__ __nv_bfloat16 g_vh[ELEMS];
__device__ __nv_bfloat16 g_vl[ELEMS];
__device__ __nv_bfloat16 g_yh[ELEMS];
__device__ __nv_bfloat16 g_yl[ELEMS];
__device__ __nv_bfloat16 g_wh[4 * CC * CC];
__device__ __nv_bfloat16 g_wl[4 * CC * CC];

// ================================================================================
// PTX helpers (base sm_103-safe: mma.sync / ldmatrix / cp.async only)
// ================================================================================
__device__ __forceinline__ uint32_t smem_u32(const void* p) {
    uint32_t a;
    asm("{ .reg .u64 t; cvta.to.shared.u64 t, %1; cvt.u32.u64 %0, t; }" : "=r"(a) : "l"(p));
    return a;
}

__device__ __forceinline__ void cp16(uint32_t dst, const void* src) {
    asm volatile("cp.async.cg.shared.global [%0], [%1], 16;" :: "r"(dst), "l"(src));
}
#define CP_COMMIT() asm volatile("cp.async.commit_group;" ::: "memory")
#define CP_WAIT(n)  asm volatile("cp.async.wait_group %0;" :: "n"(n) : "memory")

__device__ __forceinline__ void ldm_x4(uint32_t* r, uint32_t addr) {
    asm volatile("ldmatrix.sync.aligned.m8n8.x4.shared.b16 {%0,%1,%2,%3}, [%4];"
        : "=r"(r[0]), "=r"(r[1]), "=r"(r[2]), "=r"(r[3]) : "r"(addr));
}
__device__ __forceinline__ void ldm_x4_t(uint32_t* r, uint32_t addr) {
    asm volatile("ldmatrix.sync.aligned.m8n8.x4.trans.shared.b16 {%0,%1,%2,%3}, [%4];"
        : "=r"(r[0]), "=r"(r[1]), "=r"(r[2]), "=r"(r[3]) : "r"(addr));
}

__device__ __forceinline__ void mma_bf16(float* d, const uint32_t* a,
                                         uint32_t b0, uint32_t b1) {
    asm volatile(
        "mma.sync.aligned.m16n8k16.row.col.f32.bf16.bf16.f32 "
        "{%0,%1,%2,%3}, {%4,%5,%6,%7}, {%8,%9}, {%0,%1,%2,%3};"
        : "+f"(d[0]), "+f"(d[1]), "+f"(d[2]), "+f"(d[3])
        : "r"(a[0]), "r"(a[1]), "r"(a[2]), "r"(a[3]), "r"(b0), "r"(b1));
}

// SW128 swizzle on a 128B-row tile
#define SWZ(row, kbyte) (((row) << 7) + ((kbyte) ^ (((row) & 7) << 4)))

// split one fp32 into bf16 hi + residual lo, return packed pair builders
__device__ __forceinline__ uint32_t packbf2(float x, float y) {
    __nv_bfloat162 p(__float2bfloat16(x), __float2bfloat16(y));
    return *reinterpret_cast<uint32_t*>(&p);
}
__device__ __forceinline__ uint32_t packbf2_res(float x, float y, float& rx, float& ry) {
    __nv_bfloat16 hx = __float2bfloat16(x), hy = __float2bfloat16(y);
    rx = x - __bfloat162float(hx);
    ry = y - __bfloat162float(hy);
    __nv_bfloat162 p(hx, hy);
    return *reinterpret_cast<uint32_t*>(&p);
}

// ================================================================================
// split fp32 -> bf16 hi + bf16 lo (for x and weights)
// ================================================================================
__global__ __launch_bounds__(256) void split_kernel(
    const float* __restrict__ src, __nv_bfloat16* __restrict__ hi,
    __nv_bfloat16* __restrict__ lo, int n4)
{
    int i = blockIdx.x * 256 + threadIdx.x;
    if (i >= n4) return;
    float4 v = ((const float4*)src)[i];
    float r0, r1, r2, r3;
    uint32_t h01 = packbf2_res(v.x, v.y, r0, r1);
    uint32_t h23 = packbf2_res(v.z, v.w, r2, r3);
    ((uint32_t*)hi)[2 * i + 0] = h01;
    ((uint32_t*)hi)[2 * i + 1] = h23;
    ((uint32_t*)lo)[2 * i + 0] = packbf2(r0, r1);
    ((uint32_t*)lo)[2 * i + 1] = packbf2(r2, r3);
}

// ================================================================================
// bf16x3 mma.sync GEMM: 128x128 tile/CTA, 8 warps (2m x 4n), K-chunk 64,
// cp.async double-buffered. Epilogue: fp32 out (Cf) OR bf16 hi/lo split out.
// ================================================================================
#define KC 64
#define NCHUNK (CC / KC)      // 16
#define TILE_B 16384          // 128 rows x 128B (64 bf16)
#define BUF_B (4 * TILE_B)    // AH, AL, BH, BL
#define SMEM_GEMM (2 * BUF_B) // 131072

__global__ __launch_bounds__(256) void gemm_mma_kernel(
    const __nv_bfloat16* __restrict__ Ah, const __nv_bfloat16* __restrict__ Al,
    const __nv_bfloat16* __restrict__ Bh, const __nv_bfloat16* __restrict__ Bl,
    const float* __restrict__ bias, float* __restrict__ Cf,
    __nv_bfloat16* __restrict__ Oh, __nv_bfloat16* __restrict__ Ol, float scale)
{
    extern __shared__ char smem[];
    const uint32_t sbase = smem_u32(smem);
    const int tid = threadIdx.x;
    const int wid = tid >> 5;
    const int lane = tid & 31;
    const int wm = wid & 1;
    const int wn = wid >> 1;
    const int bm = blockIdx.y * 128;
    const int bn = blockIdx.x * 128;

    const __nv_bfloat16* srcs[4] = {Ah, Al, Bh, Bl};

    const int lrow = (lane & 7) + ((lane >> 3) & 1) * 8;
    const int lkb = (lane >> 4) * 16;

    float acc[4][4][4];
#pragma unroll
    for (int a = 0; a < 4; a++)
#pragma unroll
        for (int b = 0; b < 4; b++)
#pragma unroll
            for (int c = 0; c < 4; c++) acc[a][b][c] = 0.0f;

    auto load_chunk = [&](int chunk, int buf) {
        const int k0 = chunk * KC;
        const uint32_t tbu = sbase + buf * BUF_B;
#pragma unroll
        for (int part = 0; part < 4; part++) {
            const __nv_bfloat16* p = srcs[part];
            const int roff = (part < 2) ? bm : bn;
            const uint32_t db = tbu + part * TILE_B;
#pragma unroll
            for (int f = tid; f < 1024; f += 256) {
                int row = f >> 3;
                int c16 = f & 7;
                cp16(db + SWZ(row, c16 * 16),
                     p + (size_t)(roff + row) * CC + k0 + c16 * 8);
            }
        }
        CP_COMMIT();
    };

    load_chunk(0, 0);

    for (int chunk = 0; chunk < NCHUNK; chunk++) {
        const int buf = chunk & 1;
        if (chunk + 1 < NCHUNK) {
            load_chunk(chunk + 1, buf ^ 1);
            CP_WAIT(1);
        } else {
            CP_WAIT(0);
        }
        __syncthreads();

        const uint32_t tAh = sbase + buf * BUF_B;
        const uint32_t tAl = tAh + TILE_B;
        const uint32_t tBh = tAh + 2 * TILE_B;
        const uint32_t tBl = tAh + 3 * TILE_B;

#pragma unroll
        for (int ks = 0; ks < 4; ks++) {
            const int kb = ks * 32;
            uint32_t ah[4][4], al[4][4], bh[2][4], bl[2][4];
#pragma unroll
            for (int mi = 0; mi < 4; mi++) {
                int row = wm * 64 + mi * 16 + lrow;
                uint32_t off = SWZ(row, kb + lkb);
                ldm_x4(ah[mi], tAh + off);
                ldm_x4(al[mi], tAl + off);
            }
#pragma unroll
            for (int nj2 = 0; nj2 < 2; nj2++) {
                int row = wn * 32 + nj2 * 16 + lrow;
                uint32_t off = SWZ(row, kb + lkb);
                ldm_x4(bh[nj2], tBh + off);
                ldm_x4(bl[nj2], tBl + off);
            }
#pragma unroll
            for (int mi = 0; mi < 4; mi++) {
#pragma unroll
                for (int nj = 0; nj < 4; nj++) {
                    const int h = nj & 1;
                    mma_bf16(acc[mi][nj], ah[mi], bh[nj >> 1][h], bh[nj >> 1][h + 2]);
                    mma_bf16(acc[mi][nj], ah[mi], bl[nj >> 1][h], bl[nj >> 1][h + 2]);
                    mma_bf16(acc[mi][nj], al[mi], bh[nj >> 1][h], bh[nj >> 1][h + 2]);
                }
            }
        }
        __syncthreads();
    }

    // epilogue
    const int lr = lane >> 2;
    const int lc = (lane & 3) * 2;
#pragma unroll
    for (int nj = 0; nj < 4; nj++) {
        const int c = bn + wn * 32 + nj * 8 + lc;
        float b0 = 0.0f, b1 = 0.0f;
        if (bias) { b0 = bias[c]; b1 = bias[c + 1]; }
#pragma unroll
        for (int mi = 0; mi < 4; mi++) {
            const int r = bm + wm * 64 + mi * 16 + lr;
            float v0 = acc[mi][nj][0] + b0, v1 = acc[mi][nj][1] + b1;
            float v2 = acc[mi][nj][2] + b0, v3 = acc[mi][nj][3] + b1;
            if (Cf) {
                *(float2*)&Cf[(size_t)r * CC + c] = make_float2(v0, v1);
                *(float2*)&Cf[(size_t)(r + 8) * CC + c] = make_float2(v2, v3);
            } else {
                v0 *= scale; v1 *= scale; v2 *= scale; v3 *= scale;
                float r0, r1, r2, r3;
                uint32_t h01 = packbf2_res(v0, v1, r0, r1);
                uint32_t h23 = packbf2_res(v2, v3, r2, r3);
                *(uint32_t*)&Oh[(size_t)r * CC + c] = h01;
                *(uint32_t*)&Oh[(size_t)(r + 8) * CC + c] = h23;
                *(uint32_t*)&Ol[(size_t)r * CC + c] = packbf2(r0, r1);
                *(uint32_t*)&Ol[(size_t)(r + 8) * CC + c] = packbf2(r2, r3);
            }
        }
    }
}

// ================================================================================
// Flash attention via mma.sync, bf16x3 split precision everywhere.
// CTA: 128 q-rows x one (b,h); 8 warps, each m16 x n64 fragments.
// KV tiles of 64, cp.async double-buffered. Causal tile-skip + diagonal mask.
// smem: Qh,Ql (16KB ea) + 2 x (Kh,Kl,Vh,Vl 8KB ea) = 96KB
// ================================================================================
#define ATT_SMEM 98304

__global__ __launch_bounds__(256) void attn_mma_kernel(
    const __nv_bfloat16* __restrict__ qh, const __nv_bfloat16* __restrict__ ql,
    const __nv_bfloat16* __restrict__ kh, const __nv_bfloat16* __restrict__ kl,
    const __nv_bfloat16* __restrict__ vh, const __nv_bfloat16* __restrict__ vl,
    __nv_bfloat16* __restrict__ yh, __nv_bfloat16* __restrict__ yl)
{
    extern __shared__ char smem[];
    const uint32_t sb = smem_u32(smem);
    const uint32_t sQh = sb, sQl = sb + 16384;
    const uint32_t sKV = sb + 32768;   // + buf*32768: Kh@0, Kl@8K, Vh@16K, Vl@24K

    const int tid = threadIdx.x;
    const int wid = tid >> 5;
    const int lane = tid & 31;
    const int lrow = (lane & 7) + ((lane >> 3) & 1) * 8;
    const int lkb = (lane >> 4) * 16;

    const int q0 = blockIdx.x * 128;
    const int bh = blockIdx.y;
    const int b = bh >> 4;
    const int h = bh & 15;
    const size_t base = (size_t)b * TT * CC + (size_t)h * HD;

    // Q tile loads (both hi and lo): 128 rows x 128B each
#pragma unroll
    for (int f = tid; f < 2048; f += 256) {
        int mat = f >> 10, idx = f & 1023;
        int row = idx >> 3, c16 = idx & 7;
        const __nv_bfloat16* src = (mat ? ql : qh) + base + (size_t)(q0 + row) * CC + c16 * 8;
        cp16((mat ? sQl : sQh) + SWZ(row, c16 * 16), src);
    }

    const __nv_bfloat16* kvsrc[4] = {kh, kl, vh, vl};
    auto load_kv = [&](int kt, int buf) {
        const uint32_t db = sKV + buf * 32768;
#pragma unroll
        for (int f = tid; f < 2048; f += 256) {
            int mat = f >> 9, idx = f & 511;
            int row = idx >> 3, c16 = idx & 7;
            cp16(db + mat * 8192 + SWZ(row, c16 * 16),
                 kvsrc[mat] + base + (size_t)(kt * 64 + row) * CC + c16 * 8);
        }
    };

    const int nkt = 2 * (blockIdx.x + 1);
    load_kv(0, 0);
    CP_COMMIT();

    float m0 = -3.0e38f, m1 = -3.0e38f, l0 = 0.0f, l1 = 0.0f;
    float o[8][4];
#pragma unroll
    for (int nt = 0; nt < 8; nt++)
#pragma unroll
        for (int c = 0; c < 4; c++) o[nt][c] = 0.0f;

    const int q0w = q0 + 16 * wid;

    for (int kt = 0; kt < nkt; kt++) {
        const int buf = kt & 1;
        if (kt + 1 < nkt) {
            load_kv(kt + 1, buf ^ 1);
            CP_COMMIT();
            CP_WAIT(1);
        } else {
            CP_WAIT(0);
        }
        __syncthreads();

        const int kc = kt * 64;
        if (kc <= q0w + 15) {   // not fully masked for this warp
            const uint32_t bK = sKV + buf * 32768;
            const uint32_t bV = bK + 16384;

            // ---- S = Q K^T (bf16x3) ----
            float s[8][4];
#pragma unroll
            for (int nt = 0; nt < 8; nt++)
#pragma unroll
                for (int c = 0; c < 4; c++) s[nt][c] = 0.0f;

#pragma unroll
            for (int ks = 0; ks < 4; ks++) {
                const int kb = ks * 32;
                uint32_t aoff = SWZ(16 * wid + lrow, kb + lkb);
                uint32_t ah[4], al[4];
                ldm_x4(ah, sQh + aoff);
                ldm_x4(al, sQl + aoff);
#pragma unroll
                for (int nt2 = 0; nt2 < 4; nt2++) {
                    uint32_t boff = SWZ(nt2 * 16 + lrow, kb + lkb);
                    uint32_t bhf[4], blf[4];
                    ldm_x4(bhf, bK + boff);
                    ldm_x4(blf, bK + 8192 + boff);
#pragma unroll
                    for (int hh = 0; hh < 2; hh++) {
                        int nt = nt2 * 2 + hh;
                        mma_bf16(s[nt], ah, bhf[hh], bhf[hh + 2]);
                        mma_bf16(s[nt], ah, blf[hh], blf[hh + 2]);
                        mma_bf16(s[nt], al, bhf[hh], bhf[hh + 2]);
                    }
                }
            }

            // ---- causal mask on diagonal tiles ----
            if (kc + 63 > q0w) {
                const int r0 = q0w + (lane >> 2);
                const int r1 = r0 + 8;
#pragma unroll
                for (int nt = 0; nt < 8; nt++) {
                    int c0 = kc + 8 * nt + 2 * (lane & 3);
                    if (c0 > r0)     s[nt][0] = -1.0e30f;
                    if (c0 + 1 > r0) s[nt][1] = -1.0e30f;
                    if (c0 > r1)     s[nt][2] = -1.0e30f;
                    if (c0 + 1 > r1) s[nt][3] = -1.0e30f;
                }
            }

            // ---- online softmax ----
            float mt0 = -3.0e38f, mt1 = -3.0e38f;
#pragma unroll
            for (int nt = 0; nt < 8; nt++) {
                mt0 = fmaxf(mt0, fmaxf(s[nt][0], s[nt][1]));
                mt1 = fmaxf(mt1, fmaxf(s[nt][2], s[nt][3]));
            }
#pragma unroll
            for (int d = 1; d <= 2; d <<= 1) {
                mt0 = fmaxf(mt0, __shfl_xor_sync(0xffffffffu, mt0, d));
                mt1 = fmaxf(mt1, __shfl_xor_sync(0xffffffffu, mt1, d));
            }
            float mn0 = fmaxf(m0, mt0), mn1 = fmaxf(m1, mt1);
            float corr0 = __expf(m0 - mn0), corr1 = __expf(m1 - mn1);
            float ls0 = 0.0f, ls1 = 0.0f;
#pragma unroll
            for (int nt = 0; nt < 8; nt++) {
                s[nt][0] = __expf(s[nt][0] - mn0);
                s[nt][1] = __expf(s[nt][1] - mn0);
                s[nt][2] = __expf(s[nt][2] - mn1);
                s[nt][3] = __expf(s[nt][3] - mn1);
                ls0 += s[nt][0] + s[nt][1];
                ls1 += s[nt][2] + s[nt][3];
            }
#pragma unroll
            for (int d = 1; d <= 2; d <<= 1) {
                ls0 += __shfl_xor_sync(0xffffffffu, ls0, d);
                ls1 += __shfl_xor_sync(0xffffffffu, ls1, d);
            }
            l0 = l0 * corr0 + ls0;  m0 = mn0;
            l1 = l1 * corr1 + ls1;  m1 = mn1;
#pragma unroll
            for (int nt = 0; nt < 8; nt++) {
                o[nt][0] *= corr0; o[nt][1] *= corr0;
                o[nt][2] *= corr1; o[nt][3] *= corr1;
            }

            // ---- O += P V (bf16x3; P split in registers) ----
#pragma unroll
            for (int ks = 0; ks < 4; ks++) {
                // A fragments from P (accumulator layout == A layout)
                uint32_t a_h[4], a_l[4];
                float r0a, r1a;
                a_h[0] = packbf2_res(s[2 * ks][0], s[2 * ks][1], r0a, r1a);
                a_l[0] = packbf2(r0a, r1a);
                a_h[1] = packbf2_res(s[2 * ks][2], s[2 * ks][3], r0a, r1a);
                a_l[1] = packbf2(r0a, r1a);
                a_h[2] = packbf2_res(s[2 * ks + 1][0], s[2 * ks + 1][1], r0a, r1a);
                a_l[2] = packbf2(r0a, r1a);
                a_h[3] = packbf2_res(s[2 * ks + 1][2], s[2 * ks + 1][3], r0a, r1a);
                a_l[3] = packbf2(r0a, r1a);
#pragma unroll
                for (int nt2 = 0; nt2 < 4; nt2++) {
                    uint32_t voff = SWZ(ks * 16 + lrow, nt2 * 32 + lkb);
                    uint32_t bvh[4], bvl[4];
                    ldm_x4_t(bvh, bV + voff);
                    ldm_x4_t(bvl, bV + 8192 + voff);
#pragma unroll
                    for (int hh = 0; hh < 2; hh++) {
                        int nt = nt2 * 2 + hh;
                        mma_bf16(o[nt], a_h, bvh[2 * hh], bvh[2 * hh + 1]);
                        mma_bf16(o[nt], a_h, bvl[2 * hh], bvl[2 * hh + 1]);
                        mma_bf16(o[nt], a_l, bvh[2 * hh], bvh[2 * hh + 1]);
                    }
                }
            }
        }
        __syncthreads();
    }

    // ---- normalize, split hi/lo, store ----
    const float inv0 = 1.0f / l0, inv1 = 1.0f / l1;
    const int t0 = q0w + (lane >> 2);
    const int t1 = t0 + 8;
#pragma unroll
    for (int nt = 0; nt < 8; nt++) {
        const int c = 8 * nt + 2 * (lane & 3);
        const size_t o0 = base + (size_t)t0 * CC + c;
        const size_t o1 = base + (size_t)t1 * CC + c;
        float v0 = o[nt][0] * inv0, v1 = o[nt][1] * inv0;
        float v2 = o[nt][2] * inv1, v3 = o[nt][3] * inv1;
        float r0, r1, r2, r3;
        uint32_t h01 = packbf2_res(v0, v1, r0, r1);
        uint32_t h23 = packbf2_res(v2, v3, r2, r3);
        *(uint32_t*)&yh[o0] = h01;
        *(uint32_t*)&yh[o1] = h23;
        *(uint32_t*)&yl[o0] = packbf2(r0, r1);
        *(uint32_t*)&yl[o1] = packbf2(r2, r3);
    }
}

// ================================================================================
// launch
// ================================================================================
extern "C" void kernel_launch(void* const* d_in, const int* in_sizes, int n_in,
                              void* d_out, int out_size)
{
    const float* x  = (const float*)d_in[0];
    const float* Wq = (const float*)d_in[1];
    const float* bq = (const float*)d_in[2];
    const float* Wk = (const float*)d_in[3];
    const float* bk = (const float*)d_in[4];
    const float* Wv = (const float*)d_in[5];
    const float* bv = (const float*)d_in[6];
    const float* Wp = (const float*)d_in[7];
    float* out = (float*)d_out;

    __nv_bfloat16 *xh, *xl, *qh, *ql, *kh, *kl, *vh, *vl, *yh, *yl, *wh, *wl;
    cudaGetSymbolAddress((void**)&xh, g_xh);
    cudaGetSymbolAddress((void**)&xl, g_xl);
    cudaGetSymbolAddress((void**)&qh, g_qh);
    cudaGetSymbolAddress((void**)&ql, g_ql);
    cudaGetSymbolAddress((void**)&kh, g_kh);
    cudaGetSymbolAddress((void**)&kl, g_kl);
    cudaGetSymbolAddress((void**)&vh, g_vh);
    cudaGetSymbolAddress((void**)&vl, g_vl);
    cudaGetSymbolAddress((void**)&yh, g_yh);
    cudaGetSymbolAddress((void**)&yl, g_yl);
    cudaGetSymbolAddress((void**)&wh, g_wh);
    cudaGetSymbolAddress((void**)&wl, g_wl);

    const int WSZ = CC * CC;

    cudaFuncSetAttribute(gemm_mma_kernel, cudaFuncAttributeMaxDynamicSharedMemorySize,
                         SMEM_GEMM);
    cudaFuncSetAttribute(attn_mma_kernel, cudaFuncAttributeMaxDynamicSharedMemorySize,
                         ATT_SMEM);

    // splits: x and weights
    split_kernel<<<ELEMS / 4 / 256, 256>>>(x, xh, xl, ELEMS / 4);
    split_kernel<<<WSZ / 4 / 256, 256>>>(Wq, wh + 0 * WSZ, wl + 0 * WSZ, WSZ / 4);
    split_kernel<<<WSZ / 4 / 256, 256>>>(Wk, wh + 1 * WSZ, wl + 1 * WSZ, WSZ / 4);
    split_kernel<<<WSZ / 4 / 256, 256>>>(Wv, wh + 2 * WSZ, wl + 2 * WSZ, WSZ / 4);
    split_kernel<<<WSZ / 4 / 256, 256>>>(Wp, wh + 3 * WSZ, wl + 3 * WSZ, WSZ / 4);

    dim3 gg(CC / 128, MM / 128);  // (8, 64)
    // QKV projections -> bf16 hi/lo directly (Q pre-scaled by 1/sqrt(HD))
    gemm_mma_kernel<<<gg, 256, SMEM_GEMM>>>(xh, xl, wh + 0 * WSZ, wl + 0 * WSZ, bq,
                                            nullptr, qh, ql, 0.125f);
    gemm_mma_kernel<<<gg, 256, SMEM_GEMM>>>(xh, xl, wh + 1 * WSZ, wl + 1 * WSZ, bk,
                                            nullptr, kh, kl, 1.0f);
    gemm_mma_kernel<<<gg, 256, SMEM_GEMM>>>(xh, xl, wh + 2 * WSZ, wl + 2 * WSZ, bv,
                                            nullptr, vh, vl, 1.0f);

    // attention (tensor-core, bf16x3)
    attn_mma_kernel<<<dim3(TT / 128, BB * HH), 256, ATT_SMEM>>>(qh, ql, kh, kl,
                                                                vh, vl, yh, yl);

    // output projection -> fp32 out
    gemm_mma_kernel<<<gg, 256, SMEM_GEMM>>>(yh, yl, wh + 3 * WSZ, wl + 3 * WSZ,
                                            nullptr, out, nullptr, nullptr, 1.0f);
}

// round 5
// speedup vs baseline: 3.3689x; 1.1409x over previous
#include <cuda_runtime.h>
#include <cuda_bf16.h>
#include <cuda_fp16.h>
#include <cstdint>
#include <cstddef>

// Problem constants
#define BB 4
#define TT 2048
#define CC 1024
#define HH 16
#define HD 64
#define MM (BB * TT)          // 8192 rows

// ---------------- scratch (static device globals; no allocation) ----------------
#define ELEMS (BB * TT * CC)  // 8,388,608
__device__ __nv_bfloat16 g_xh[ELEMS];
__device__ __nv_bfloat16 g_xl[ELEMS];
__device__ __half        g_qh[ELEMS];   // Q: single fp16 (pre-scaled)
__device__ __half        g_kh[ELEMS];
__device__ __half        g_kl[ELEMS];
__device__ __half        g_vh[ELEMS];
__device__ __half        g_vl[ELEMS];
__device__ __nv_bfloat16 g_yh[ELEMS];
__device__ __nv_bfloat16 g_yl[ELEMS];
__device__ __nv_bfloat16 g_wh[4 * CC * CC];
__device__ __nv_bfloat16 g_wl[4 * CC * CC];

// ================================================================================
// PTX helpers (base sm_103-safe: mma.sync / ldmatrix / cp.async only)
// ================================================================================
__device__ __forceinline__ uint32_t smem_u32(const void* p) {
    uint32_t a;
    asm("{ .reg .u64 t; cvta.to.shared.u64 t, %1; cvt.u32.u64 %0, t; }" : "=r"(a) : "l"(p));
    return a;
}

__device__ __forceinline__ void cp16(uint32_t dst, const void* src) {
    asm volatile("cp.async.cg.shared.global [%0], [%1], 16;" :: "r"(dst), "l"(src));
}
#define CP_COMMIT() asm volatile("cp.async.commit_group;" ::: "memory")
#define CP_WAIT(n)  asm volatile("cp.async.wait_group %0;" :: "n"(n) : "memory")

__device__ __forceinline__ void ldm_x4(uint32_t* r, uint32_t addr) {
    asm volatile("ldmatrix.sync.aligned.m8n8.x4.shared.b16 {%0,%1,%2,%3}, [%4];"
        : "=r"(r[0]), "=r"(r[1]), "=r"(r[2]), "=r"(r[3]) : "r"(addr));
}
__device__ __forceinline__ void ldm_x4_t(uint32_t* r, uint32_t addr) {
    asm volatile("ldmatrix.sync.aligned.m8n8.x4.trans.shared.b16 {%0,%1,%2,%3}, [%4];"
        : "=r"(r[0]), "=r"(r[1]), "=r"(r[2]), "=r"(r[3]) : "r"(addr));
}

__device__ __forceinline__ void mma_bf16(float* d, const uint32_t* a,
                                         uint32_t b0, uint32_t b1) {
    asm volatile(
        "mma.sync.aligned.m16n8k16.row.col.f32.bf16.bf16.f32 "
        "{%0,%1,%2,%3}, {%4,%5,%6,%7}, {%8,%9}, {%0,%1,%2,%3};"
        : "+f"(d[0]), "+f"(d[1]), "+f"(d[2]), "+f"(d[3])
        : "r"(a[0]), "r"(a[1]), "r"(a[2]), "r"(a[3]), "r"(b0), "r"(b1));
}
__device__ __forceinline__ void mma_f16(float* d, const uint32_t* a,
                                        uint32_t b0, uint32_t b1) {
    asm volatile(
        "mma.sync.aligned.m16n8k16.row.col.f32.f16.f16.f32 "
        "{%0,%1,%2,%3}, {%4,%5,%6,%7}, {%8,%9}, {%0,%1,%2,%3};"
        : "+f"(d[0]), "+f"(d[1]), "+f"(d[2]), "+f"(d[3])
        : "r"(a[0]), "r"(a[1]), "r"(a[2]), "r"(a[3]), "r"(b0), "r"(b1));
}

// SW128 swizzle on a 128B-row tile
#define SWZ(row, kbyte) (((row) << 7) + ((kbyte) ^ (((row) & 7) << 4)))

// bf16 pack helpers
__device__ __forceinline__ uint32_t packbf2(float x, float y) {
    __nv_bfloat162 p(__float2bfloat16(x), __float2bfloat16(y));
    return *reinterpret_cast<uint32_t*>(&p);
}
__device__ __forceinline__ uint32_t packbf2_res(float x, float y, float& rx, float& ry) {
    __nv_bfloat16 hx = __float2bfloat16(x), hy = __float2bfloat16(y);
    rx = x - __bfloat162float(hx);
    ry = y - __bfloat162float(hy);
    __nv_bfloat162 p(hx, hy);
    return *reinterpret_cast<uint32_t*>(&p);
}
// fp16 pack helpers
__device__ __forceinline__ uint32_t packh2(float x, float y) {
    __half2 p = __floats2half2_rn(x, y);
    return *reinterpret_cast<uint32_t*>(&p);
}
__device__ __forceinline__ uint32_t packh2_res(float x, float y, float& rx, float& ry) {
    __half hx = __float2half_rn(x), hy = __float2half_rn(y);
    rx = x - __half2float(hx);
    ry = y - __half2float(hy);
    __half2 p(hx, hy);
    return *reinterpret_cast<uint32_t*>(&p);
}

// ================================================================================
// split fp32 -> bf16 hi + bf16 lo (for x and weights)
// ================================================================================
__global__ __launch_bounds__(256) void split_kernel(
    const float* __restrict__ src, __nv_bfloat16* __restrict__ hi,
    __nv_bfloat16* __restrict__ lo, int n4)
{
    int i = blockIdx.x * 256 + threadIdx.x;
    if (i >= n4) return;
    float4 v = ((const float4*)src)[i];
    float r0, r1, r2, r3;
    uint32_t h01 = packbf2_res(v.x, v.y, r0, r1);
    uint32_t h23 = packbf2_res(v.z, v.w, r2, r3);
    ((uint32_t*)hi)[2 * i + 0] = h01;
    ((uint32_t*)hi)[2 * i + 1] = h23;
    ((uint32_t*)lo)[2 * i + 0] = packbf2(r0, r1);
    ((uint32_t*)lo)[2 * i + 1] = packbf2(r2, r3);
}

// ================================================================================
// bf16x3 mma.sync GEMM: 128x128 tile/CTA, 8 warps (2m x 4n), K-chunk 64,
// cp.async double-buffered.
// Epilogue modes: 0 = fp32 -> Cf;  1 = bf16 hi/lo -> O1/O2;
//                 2 = fp16 hi/lo -> O1/O2;  3 = fp16 single -> O1.
// ================================================================================
#define KC 64
#define NCHUNK (CC / KC)      // 16
#define TILE_B 16384          // 128 rows x 128B (64 bf16)
#define BUF_B (4 * TILE_B)    // AH, AL, BH, BL
#define SMEM_GEMM (2 * BUF_B) // 131072

__global__ __launch_bounds__(256) void gemm_mma_kernel(
    const __nv_bfloat16* __restrict__ Ah, const __nv_bfloat16* __restrict__ Al,
    const __nv_bfloat16* __restrict__ Bh, const __nv_bfloat16* __restrict__ Bl,
    const float* __restrict__ bias, float* __restrict__ Cf,
    void* __restrict__ O1, void* __restrict__ O2, float scale, int mode)
{
    extern __shared__ char smem[];
    const uint32_t sbase = smem_u32(smem);
    const int tid = threadIdx.x;
    const int wid = tid >> 5;
    const int lane = tid & 31;
    const int wm = wid & 1;
    const int wn = wid >> 1;
    const int bm = blockIdx.y * 128;
    const int bn = blockIdx.x * 128;

    const __nv_bfloat16* srcs[4] = {Ah, Al, Bh, Bl};

    const int lrow = (lane & 7) + ((lane >> 3) & 1) * 8;
    const int lkb = (lane >> 4) * 16;

    float acc[4][4][4];
#pragma unroll
    for (int a = 0; a < 4; a++)
#pragma unroll
        for (int b = 0; b < 4; b++)
#pragma unroll
            for (int c = 0; c < 4; c++) acc[a][b][c] = 0.0f;

    auto load_chunk = [&](int chunk, int buf) {
        const int k0 = chunk * KC;
        const uint32_t tbu = sbase + buf * BUF_B;
#pragma unroll
        for (int part = 0; part < 4; part++) {
            const __nv_bfloat16* p = srcs[part];
            const int roff = (part < 2) ? bm : bn;
            const uint32_t db = tbu + part * TILE_B;
#pragma unroll
            for (int f = tid; f < 1024; f += 256) {
                int row = f >> 3;
                int c16 = f & 7;
                cp16(db + SWZ(row, c16 * 16),
                     p + (size_t)(roff + row) * CC + k0 + c16 * 8);
            }
        }
        CP_COMMIT();
    };

    load_chunk(0, 0);

    for (int chunk = 0; chunk < NCHUNK; chunk++) {
        const int buf = chunk & 1;
        if (chunk + 1 < NCHUNK) {
            load_chunk(chunk + 1, buf ^ 1);
            CP_WAIT(1);
        } else {
            CP_WAIT(0);
        }
        __syncthreads();

        const uint32_t tAh = sbase + buf * BUF_B;
        const uint32_t tAl = tAh + TILE_B;
        const uint32_t tBh = tAh + 2 * TILE_B;
        const uint32_t tBl = tAh + 3 * TILE_B;

#pragma unroll
        for (int ks = 0; ks < 4; ks++) {
            const int kb = ks * 32;
            uint32_t ah[4][4], al[4][4], bh[2][4], bl[2][4];
#pragma unroll
            for (int mi = 0; mi < 4; mi++) {
                int row = wm * 64 + mi * 16 + lrow;
                uint32_t off = SWZ(row, kb + lkb);
                ldm_x4(ah[mi], tAh + off);
                ldm_x4(al[mi], tAl + off);
            }
#pragma unroll
            for (int nj2 = 0; nj2 < 2; nj2++) {
                int row = wn * 32 + nj2 * 16 + lrow;
                uint32_t off = SWZ(row, kb + lkb);
                ldm_x4(bh[nj2], tBh + off);
                ldm_x4(bl[nj2], tBl + off);
            }
#pragma unroll
            for (int mi = 0; mi < 4; mi++) {
#pragma unroll
                for (int nj = 0; nj < 4; nj++) {
                    const int h = nj & 1;
                    mma_bf16(acc[mi][nj], ah[mi], bh[nj >> 1][h], bh[nj >> 1][h + 2]);
                    mma_bf16(acc[mi][nj], ah[mi], bl[nj >> 1][h], bl[nj >> 1][h + 2]);
                    mma_bf16(acc[mi][nj], al[mi], bh[nj >> 1][h], bh[nj >> 1][h + 2]);
                }
            }
        }
        __syncthreads();
    }

    // epilogue
    const int lr = lane >> 2;
    const int lc = (lane & 3) * 2;
#pragma unroll
    for (int nj = 0; nj < 4; nj++) {
        const int c = bn + wn * 32 + nj * 8 + lc;
        float b0 = 0.0f, b1 = 0.0f;
        if (bias) { b0 = bias[c]; b1 = bias[c + 1]; }
#pragma unroll
        for (int mi = 0; mi < 4; mi++) {
            const int r = bm + wm * 64 + mi * 16 + lr;
            float v0 = acc[mi][nj][0] + b0, v1 = acc[mi][nj][1] + b1;
            float v2 = acc[mi][nj][2] + b0, v3 = acc[mi][nj][3] + b1;
            const size_t p0 = (size_t)r * CC + c;
            const size_t p1 = (size_t)(r + 8) * CC + c;
            if (mode == 0) {
                *(float2*)&Cf[p0] = make_float2(v0, v1);
                *(float2*)&Cf[p1] = make_float2(v2, v3);
            } else {
                v0 *= scale; v1 *= scale; v2 *= scale; v3 *= scale;
                if (mode == 1) {
                    float r0, r1, r2, r3;
                    uint32_t h01 = packbf2_res(v0, v1, r0, r1);
                    uint32_t h23 = packbf2_res(v2, v3, r2, r3);
                    *(uint32_t*)((__nv_bfloat16*)O1 + p0) = h01;
                    *(uint32_t*)((__nv_bfloat16*)O1 + p1) = h23;
                    *(uint32_t*)((__nv_bfloat16*)O2 + p0) = packbf2(r0, r1);
                    *(uint32_t*)((__nv_bfloat16*)O2 + p1) = packbf2(r2, r3);
                } else if (mode == 2) {
                    float r0, r1, r2, r3;
                    uint32_t h01 = packh2_res(v0, v1, r0, r1);
                    uint32_t h23 = packh2_res(v2, v3, r2, r3);
                    *(uint32_t*)((__half*)O1 + p0) = h01;
                    *(uint32_t*)((__half*)O1 + p1) = h23;
                    *(uint32_t*)((__half*)O2 + p0) = packh2(r0, r1);
                    *(uint32_t*)((__half*)O2 + p1) = packh2(r2, r3);
                } else {  // mode 3: fp16 single
                    *(uint32_t*)((__half*)O1 + p0) = packh2(v0, v1);
                    *(uint32_t*)((__half*)O1 + p1) = packh2(v2, v3);
                }
            }
        }
    }
}

// ================================================================================
// Flash attention via mma.sync, fp16: Q single, K hi/lo, V hi/lo, P single.
// CTA: 128 q-rows x one (b,h); 8 warps, each m16 x n64 fragments.
// KV tiles of 64, cp.async double-buffered. Causal tile-skip + diagonal mask.
// smem: Q 16KB + 2 x (Kh,Kl,Vh,Vl 8KB ea) = 80KB
// ================================================================================
#define ATT_SMEM 81920

__global__ __launch_bounds__(256) void attn_mma_kernel(
    const __half* __restrict__ qh,
    const __half* __restrict__ kh, const __half* __restrict__ kl,
    const __half* __restrict__ vh, const __half* __restrict__ vl,
    __nv_bfloat16* __restrict__ yh, __nv_bfloat16* __restrict__ yl)
{
    extern __shared__ char smem[];
    const uint32_t sb = smem_u32(smem);
    const uint32_t sQ = sb;
    const uint32_t sKV = sb + 16384;   // + buf*32768: Kh@0, Kl@8K, Vh@16K, Vl@24K

    const int tid = threadIdx.x;
    const int wid = tid >> 5;
    const int lane = tid & 31;
    const int lrow = (lane & 7) + ((lane >> 3) & 1) * 8;
    const int lkb = (lane >> 4) * 16;

    const int q0 = blockIdx.x * 128;
    const int bh = blockIdx.y;
    const int b = bh >> 4;
    const int h = bh & 15;
    const size_t base = (size_t)b * TT * CC + (size_t)h * HD;

    // Q tile load (single fp16): 128 rows x 128B
#pragma unroll
    for (int f = tid; f < 1024; f += 256) {
        int row = f >> 3, c16 = f & 7;
        cp16(sQ + SWZ(row, c16 * 16), qh + base + (size_t)(q0 + row) * CC + c16 * 8);
    }

    const __half* kvsrc[4] = {kh, kl, vh, vl};
    auto load_kv = [&](int kt, int buf) {
        const uint32_t db = sKV + buf * 32768;
#pragma unroll
        for (int f = tid; f < 2048; f += 256) {
            int mat = f >> 9, idx = f & 511;
            int row = idx >> 3, c16 = idx & 7;
            cp16(db + mat * 8192 + SWZ(row, c16 * 16),
                 kvsrc[mat] + base + (size_t)(kt * 64 + row) * CC + c16 * 8);
        }
    };

    const int nkt = 2 * (blockIdx.x + 1);
    load_kv(0, 0);
    CP_COMMIT();

    float m0 = -3.0e38f, m1 = -3.0e38f, l0 = 0.0f, l1 = 0.0f;
    float o[8][4];
#pragma unroll
    for (int nt = 0; nt < 8; nt++)
#pragma unroll
        for (int c = 0; c < 4; c++) o[nt][c] = 0.0f;

    const int q0w = q0 + 16 * wid;

    for (int kt = 0; kt < nkt; kt++) {
        const int buf = kt & 1;
        if (kt + 1 < nkt) {
            load_kv(kt + 1, buf ^ 1);
            CP_COMMIT();
            CP_WAIT(1);
        } else {
            CP_WAIT(0);
        }
        __syncthreads();

        const int kc = kt * 64;
        if (kc <= q0w + 15) {   // not fully masked for this warp
            const uint32_t bK = sKV + buf * 32768;
            const uint32_t bKl = bK + 8192;
            const uint32_t bV = bK + 16384;
            const uint32_t bVl = bK + 24576;

            // ---- S = Q K^T (Q single fp16, K fp16 hi+lo) ----
            float s[8][4];
#pragma unroll
            for (int nt = 0; nt < 8; nt++)
#pragma unroll
                for (int c = 0; c < 4; c++) s[nt][c] = 0.0f;

#pragma unroll
            for (int ks = 0; ks < 4; ks++) {
                const int kb = ks * 32;
                uint32_t a[4];
                ldm_x4(a, sQ + SWZ(16 * wid + lrow, kb + lkb));
#pragma unroll
                for (int nt2 = 0; nt2 < 4; nt2++) {
                    uint32_t boff = SWZ(nt2 * 16 + lrow, kb + lkb);
                    uint32_t bhf[4], blf[4];
                    ldm_x4(bhf, bK + boff);
                    ldm_x4(blf, bKl + boff);
#pragma unroll
                    for (int hh = 0; hh < 2; hh++) {
                        int nt = nt2 * 2 + hh;
                        mma_f16(s[nt], a, bhf[hh], bhf[hh + 2]);
                        mma_f16(s[nt], a, blf[hh], blf[hh + 2]);
                    }
                }
            }

            // ---- causal mask on diagonal tiles ----
            if (kc + 63 > q0w) {
                const int r0 = q0w + (lane >> 2);
                const int r1 = r0 + 8;
#pragma unroll
                for (int nt = 0; nt < 8; nt++) {
                    int c0 = kc + 8 * nt + 2 * (lane & 3);
                    if (c0 > r0)     s[nt][0] = -1.0e30f;
                    if (c0 + 1 > r0) s[nt][1] = -1.0e30f;
                    if (c0 > r1)     s[nt][2] = -1.0e30f;
                    if (c0 + 1 > r1) s[nt][3] = -1.0e30f;
                }
            }

            // ---- online softmax ----
            float mt0 = -3.0e38f, mt1 = -3.0e38f;
#pragma unroll
            for (int nt = 0; nt < 8; nt++) {
                mt0 = fmaxf(mt0, fmaxf(s[nt][0], s[nt][1]));
                mt1 = fmaxf(mt1, fmaxf(s[nt][2], s[nt][3]));
            }
#pragma unroll
            for (int d = 1; d <= 2; d <<= 1) {
                mt0 = fmaxf(mt0, __shfl_xor_sync(0xffffffffu, mt0, d));
                mt1 = fmaxf(mt1, __shfl_xor_sync(0xffffffffu, mt1, d));
            }
            float mn0 = fmaxf(m0, mt0), mn1 = fmaxf(m1, mt1);
            float corr0 = __expf(m0 - mn0), corr1 = __expf(m1 - mn1);
            float ls0 = 0.0f, ls1 = 0.0f;
#pragma unroll
            for (int nt = 0; nt < 8; nt++) {
                s[nt][0] = __expf(s[nt][0] - mn0);
                s[nt][1] = __expf(s[nt][1] - mn0);
                s[nt][2] = __expf(s[nt][2] - mn1);
                s[nt][3] = __expf(s[nt][3] - mn1);
                ls0 += s[nt][0] + s[nt][1];
                ls1 += s[nt][2] + s[nt][3];
            }
#pragma unroll
            for (int d = 1; d <= 2; d <<= 1) {
                ls0 += __shfl_xor_sync(0xffffffffu, ls0, d);
                ls1 += __shfl_xor_sync(0xffffffffu, ls1, d);
            }
            l0 = l0 * corr0 + ls0;  m0 = mn0;
            l1 = l1 * corr1 + ls1;  m1 = mn1;
#pragma unroll
            for (int nt = 0; nt < 8; nt++) {
                o[nt][0] *= corr0; o[nt][1] *= corr0;
                o[nt][2] *= corr1; o[nt][3] *= corr1;
            }

            // ---- O += P V (P single fp16, V fp16 hi+lo) ----
#pragma unroll
            for (int ks = 0; ks < 4; ks++) {
                uint32_t a[4];
                a[0] = packh2(s[2 * ks][0], s[2 * ks][1]);
                a[1] = packh2(s[2 * ks][2], s[2 * ks][3]);
                a[2] = packh2(s[2 * ks + 1][0], s[2 * ks + 1][1]);
                a[3] = packh2(s[2 * ks + 1][2], s[2 * ks + 1][3]);
#pragma unroll
                for (int nt2 = 0; nt2 < 4; nt2++) {
                    uint32_t voff = SWZ(ks * 16 + lrow, nt2 * 32 + lkb);
                    uint32_t bvh[4], bvl[4];
                    ldm_x4_t(bvh, bV + voff);
                    ldm_x4_t(bvl, bVl + voff);
#pragma unroll
                    for (int hh = 0; hh < 2; hh++) {
                        int nt = nt2 * 2 + hh;
                        mma_f16(o[nt], a, bvh[2 * hh], bvh[2 * hh + 1]);
                        mma_f16(o[nt], a, bvl[2 * hh], bvl[2 * hh + 1]);
                    }
                }
            }
        }
        __syncthreads();
    }

    // ---- normalize, split bf16 hi/lo, store ----
    const float inv0 = 1.0f / l0, inv1 = 1.0f / l1;
    const int t0 = q0w + (lane >> 2);
    const int t1 = t0 + 8;
#pragma unroll
    for (int nt = 0; nt < 8; nt++) {
        const int c = 8 * nt + 2 * (lane & 3);
        const size_t o0 = base + (size_t)t0 * CC + c;
        const size_t o1 = base + (size_t)t1 * CC + c;
        float v0 = o[nt][0] * inv0, v1 = o[nt][1] * inv0;
        float v2 = o[nt][2] * inv1, v3 = o[nt][3] * inv1;
        float r0, r1, r2, r3;
        uint32_t h01 = packbf2_res(v0, v1, r0, r1);
        uint32_t h23 = packbf2_res(v2, v3, r2, r3);
        *(uint32_t*)&yh[o0] = h01;
        *(uint32_t*)&yh[o1] = h23;
        *(uint32_t*)&yl[o0] = packbf2(r0, r1);
        *(uint32_t*)&yl[o1] = packbf2(r2, r3);
    }
}

// ================================================================================
// launch
// ================================================================================
extern "C" void kernel_launch(void* const* d_in, const int* in_sizes, int n_in,
                              void* d_out, int out_size)
{
    const float* x  = (const float*)d_in[0];
    const float* Wq = (const float*)d_in[1];
    const float* bq = (const float*)d_in[2];
    const float* Wk = (const float*)d_in[3];
    const float* bk = (const float*)d_in[4];
    const float* Wv = (const float*)d_in[5];
    const float* bv = (const float*)d_in[6];
    const float* Wp = (const float*)d_in[7];
    float* out = (float*)d_out;

    __nv_bfloat16 *xh, *xl, *yh, *yl, *wh, *wl;
    __half *qh, *kh, *kl, *vh, *vl;
    cudaGetSymbolAddress((void**)&xh, g_xh);
    cudaGetSymbolAddress((void**)&xl, g_xl);
    cudaGetSymbolAddress((void**)&qh, g_qh);
    cudaGetSymbolAddress((void**)&kh, g_kh);
    cudaGetSymbolAddress((void**)&kl, g_kl);
    cudaGetSymbolAddress((void**)&vh, g_vh);
    cudaGetSymbolAddress((void**)&vl, g_vl);
    cudaGetSymbolAddress((void**)&yh, g_yh);
    cudaGetSymbolAddress((void**)&yl, g_yl);
    cudaGetSymbolAddress((void**)&wh, g_wh);
    cudaGetSymbolAddress((void**)&wl, g_wl);

    const int WSZ = CC * CC;

    cudaFuncSetAttribute(gemm_mma_kernel, cudaFuncAttributeMaxDynamicSharedMemorySize,
                         SMEM_GEMM);
    cudaFuncSetAttribute(attn_mma_kernel, cudaFuncAttributeMaxDynamicSharedMemorySize,
                         ATT_SMEM);

    // splits: x and weights
    split_kernel<<<ELEMS / 4 / 256, 256>>>(x, xh, xl, ELEMS / 4);
    split_kernel<<<WSZ / 4 / 256, 256>>>(Wq, wh + 0 * WSZ, wl + 0 * WSZ, WSZ / 4);
    split_kernel<<<WSZ / 4 / 256, 256>>>(Wk, wh + 1 * WSZ, wl + 1 * WSZ, WSZ / 4);
    split_kernel<<<WSZ / 4 / 256, 256>>>(Wv, wh + 2 * WSZ, wl + 2 * WSZ, WSZ / 4);
    split_kernel<<<WSZ / 4 / 256, 256>>>(Wp, wh + 3 * WSZ, wl + 3 * WSZ, WSZ / 4);

    dim3 gg(CC / 128, MM / 128);  // (8, 64)
    // Q -> fp16 single (pre-scaled by 1/sqrt(HD)); K,V -> fp16 hi/lo
    gemm_mma_kernel<<<gg, 256, SMEM_GEMM>>>(xh, xl, wh + 0 * WSZ, wl + 0 * WSZ, bq,
                                            nullptr, qh, nullptr, 0.125f, 3);
    gemm_mma_kernel<<<gg, 256, SMEM_GEMM>>>(xh, xl, wh + 1 * WSZ, wl + 1 * WSZ, bk,
                                            nullptr, kh, kl, 1.0f, 2);
    gemm_mma_kernel<<<gg, 256, SMEM_GEMM>>>(xh, xl, wh + 2 * WSZ, wl + 2 * WSZ, bv,
                                            nullptr, vh, vl, 1.0f, 2);

    // attention (tensor-core fp16, 2+2 MMA terms)
    attn_mma_kernel<<<dim3(TT / 128, BB * HH), 256, ATT_SMEM>>>(qh, kh, kl,
                                                                vh, vl, yh, yl);

    // output projection -> fp32 out
    gemm_mma_kernel<<<gg, 256, SMEM_GEMM>>>(yh, yl, wh + 3 * WSZ, wl + 3 * WSZ,
                                            nullptr, out, nullptr, nullptr, 1.0f, 0);
}

// round 6
// speedup vs baseline: 4.5859x; 1.3612x over previous
#include <cuda_runtime.h>
#include <cuda_bf16.h>
#include <cuda_fp16.h>
#include <cstdint>
#include <cstddef>

// Problem constants
#define BB 4
#define TT 2048
#define CC 1024
#define HH 16
#define HD 64
#define MM (BB * TT)          // 8192 rows

// ---------------- scratch (static device globals; no allocation) ----------------
#define ELEMS (BB * TT * CC)  // 8,388,608
__device__ __half g_xh[ELEMS];
__device__ __half g_xl[ELEMS];
__device__ __half g_qh[ELEMS];   // Q: single fp16 (pre-scaled)
__device__ __half g_kh[ELEMS];
__device__ __half g_kl[ELEMS];
__device__ __half g_vh[ELEMS];
__device__ __half g_vl[ELEMS];
__device__ __half g_yh[ELEMS];
__device__ __half g_yl[ELEMS];
__device__ __half g_w[4 * CC * CC];   // weights: single fp16

// ================================================================================
// PTX helpers (base sm_103-safe: mma.sync / ldmatrix / cp.async only)
// ================================================================================
__device__ __forceinline__ uint32_t smem_u32(const void* p) {
    uint32_t a;
    asm("{ .reg .u64 t; cvta.to.shared.u64 t, %1; cvt.u32.u64 %0, t; }" : "=r"(a) : "l"(p));
    return a;
}

__device__ __forceinline__ void cp16(uint32_t dst, const void* src) {
    asm volatile("cp.async.cg.shared.global [%0], [%1], 16;" :: "r"(dst), "l"(src));
}
#define CP_COMMIT() asm volatile("cp.async.commit_group;" ::: "memory")
#define CP_WAIT(n)  asm volatile("cp.async.wait_group %0;" :: "n"(n) : "memory")

__device__ __forceinline__ void ldm_x4(uint32_t* r, uint32_t addr) {
    asm volatile("ldmatrix.sync.aligned.m8n8.x4.shared.b16 {%0,%1,%2,%3}, [%4];"
        : "=r"(r[0]), "=r"(r[1]), "=r"(r[2]), "=r"(r[3]) : "r"(addr));
}
__device__ __forceinline__ void ldm_x4_t(uint32_t* r, uint32_t addr) {
    asm volatile("ldmatrix.sync.aligned.m8n8.x4.trans.shared.b16 {%0,%1,%2,%3}, [%4];"
        : "=r"(r[0]), "=r"(r[1]), "=r"(r[2]), "=r"(r[3]) : "r"(addr));
}

__device__ __forceinline__ void mma_f16(float* d, const uint32_t* a,
                                        uint32_t b0, uint32_t b1) {
    asm volatile(
        "mma.sync.aligned.m16n8k16.row.col.f32.f16.f16.f32 "
        "{%0,%1,%2,%3}, {%4,%5,%6,%7}, {%8,%9}, {%0,%1,%2,%3};"
        : "+f"(d[0]), "+f"(d[1]), "+f"(d[2]), "+f"(d[3])
        : "r"(a[0]), "r"(a[1]), "r"(a[2]), "r"(a[3]), "r"(b0), "r"(b1));
}

// SW128 swizzle on a 128B-row tile
#define SWZ(row, kbyte) (((row) << 7) + ((kbyte) ^ (((row) & 7) << 4)))

// fp16 pack helpers
__device__ __forceinline__ uint32_t packh2(float x, float y) {
    __half2 p = __floats2half2_rn(x, y);
    return *reinterpret_cast<uint32_t*>(&p);
}
__device__ __forceinline__ uint32_t packh2_res(float x, float y, float& rx, float& ry) {
    __half hx = __float2half_rn(x), hy = __float2half_rn(y);
    rx = x - __half2float(hx);
    ry = y - __half2float(hy);
    __half2 p(hx, hy);
    return *reinterpret_cast<uint32_t*>(&p);
}

// ================================================================================
// split fp32 -> fp16 hi + fp16 lo (activations)
// ================================================================================
__global__ __launch_bounds__(256) void split_h_kernel(
    const float* __restrict__ src, __half* __restrict__ hi,
    __half* __restrict__ lo, int n4)
{
    int i = blockIdx.x * 256 + threadIdx.x;
    if (i >= n4) return;
    float4 v = ((const float4*)src)[i];
    float r0, r1, r2, r3;
    uint32_t h01 = packh2_res(v.x, v.y, r0, r1);
    uint32_t h23 = packh2_res(v.z, v.w, r2, r3);
    ((uint32_t*)hi)[2 * i + 0] = h01;
    ((uint32_t*)hi)[2 * i + 1] = h23;
    ((uint32_t*)lo)[2 * i + 0] = packh2(r0, r1);
    ((uint32_t*)lo)[2 * i + 1] = packh2(r2, r3);
}

// fp32 -> fp16 single (weights)
__global__ __launch_bounds__(256) void conv_h_kernel(
    const float* __restrict__ src, __half* __restrict__ dst, int n4)
{
    int i = blockIdx.x * 256 + threadIdx.x;
    if (i >= n4) return;
    float4 v = ((const float4*)src)[i];
    ((uint32_t*)dst)[2 * i + 0] = packh2(v.x, v.y);
    ((uint32_t*)dst)[2 * i + 1] = packh2(v.z, v.w);
}

// ================================================================================
// fp16 2-term mma.sync GEMM: C[M,N] = (Ah+Al)[M,K] @ W[N,K]^T (+bias)
// 128x128 tile/CTA, 8 warps (2m x 4n), K-chunk 64, cp.async double-buffered.
// Epilogue modes: 0 = fp32 -> Cf;  2 = fp16 hi/lo -> O1/O2;  3 = fp16 single -> O1.
// ================================================================================
#define KC 64
#define NCHUNK (CC / KC)      // 16
#define TILE_B 16384          // 128 rows x 128B (64 fp16)
#define BUF_B (3 * TILE_B)    // AH, AL, B
#define SMEM_GEMM (2 * BUF_B) // 98304

__global__ __launch_bounds__(256) void gemm_mma_kernel(
    const __half* __restrict__ Ah, const __half* __restrict__ Al,
    const __half* __restrict__ B,
    const float* __restrict__ bias, float* __restrict__ Cf,
    void* __restrict__ O1, void* __restrict__ O2, float scale, int mode)
{
    extern __shared__ char smem[];
    const uint32_t sbase = smem_u32(smem);
    const int tid = threadIdx.x;
    const int wid = tid >> 5;
    const int lane = tid & 31;
    const int wm = wid & 1;
    const int wn = wid >> 1;
    const int bm = blockIdx.y * 128;
    const int bn = blockIdx.x * 128;

    const __half* srcs[3] = {Ah, Al, B};

    const int lrow = (lane & 7) + ((lane >> 3) & 1) * 8;
    const int lkb = (lane >> 4) * 16;

    float acc[4][4][4];
#pragma unroll
    for (int a = 0; a < 4; a++)
#pragma unroll
        for (int b = 0; b < 4; b++)
#pragma unroll
            for (int c = 0; c < 4; c++) acc[a][b][c] = 0.0f;

    auto load_chunk = [&](int chunk, int buf) {
        const int k0 = chunk * KC;
        const uint32_t tbu = sbase + buf * BUF_B;
#pragma unroll
        for (int part = 0; part < 3; part++) {
            const __half* p = srcs[part];
            const int roff = (part < 2) ? bm : bn;
            const uint32_t db = tbu + part * TILE_B;
#pragma unroll
            for (int f = tid; f < 1024; f += 256) {
                int row = f >> 3;
                int c16 = f & 7;
                cp16(db + SWZ(row, c16 * 16),
                     p + (size_t)(roff + row) * CC + k0 + c16 * 8);
            }
        }
        CP_COMMIT();
    };

    load_chunk(0, 0);

    for (int chunk = 0; chunk < NCHUNK; chunk++) {
        const int buf = chunk & 1;
        if (chunk + 1 < NCHUNK) {
            load_chunk(chunk + 1, buf ^ 1);
            CP_WAIT(1);
        } else {
            CP_WAIT(0);
        }
        __syncthreads();

        const uint32_t tAh = sbase + buf * BUF_B;
        const uint32_t tAl = tAh + TILE_B;
        const uint32_t tB  = tAh + 2 * TILE_B;

#pragma unroll
        for (int ks = 0; ks < 4; ks++) {
            const int kb = ks * 32;
            uint32_t ah[4][4], al[4][4], bf[2][4];
#pragma unroll
            for (int mi = 0; mi < 4; mi++) {
                int row = wm * 64 + mi * 16 + lrow;
                uint32_t off = SWZ(row, kb + lkb);
                ldm_x4(ah[mi], tAh + off);
                ldm_x4(al[mi], tAl + off);
            }
#pragma unroll
            for (int nj2 = 0; nj2 < 2; nj2++) {
                int row = wn * 32 + nj2 * 16 + lrow;
                ldm_x4(bf[nj2], tB + SWZ(row, kb + lkb));
            }
#pragma unroll
            for (int mi = 0; mi < 4; mi++) {
#pragma unroll
                for (int nj = 0; nj < 4; nj++) {
                    const int h = nj & 1;
                    mma_f16(acc[mi][nj], ah[mi], bf[nj >> 1][h], bf[nj >> 1][h + 2]);
                    mma_f16(acc[mi][nj], al[mi], bf[nj >> 1][h], bf[nj >> 1][h + 2]);
                }
            }
        }
        __syncthreads();
    }

    // epilogue
    const int lr = lane >> 2;
    const int lc = (lane & 3) * 2;
#pragma unroll
    for (int nj = 0; nj < 4; nj++) {
        const int c = bn + wn * 32 + nj * 8 + lc;
        float b0 = 0.0f, b1 = 0.0f;
        if (bias) { b0 = bias[c]; b1 = bias[c + 1]; }
#pragma unroll
        for (int mi = 0; mi < 4; mi++) {
            const int r = bm + wm * 64 + mi * 16 + lr;
            float v0 = acc[mi][nj][0] + b0, v1 = acc[mi][nj][1] + b1;
            float v2 = acc[mi][nj][2] + b0, v3 = acc[mi][nj][3] + b1;
            const size_t p0 = (size_t)r * CC + c;
            const size_t p1 = (size_t)(r + 8) * CC + c;
            if (mode == 0) {
                *(float2*)&Cf[p0] = make_float2(v0, v1);
                *(float2*)&Cf[p1] = make_float2(v2, v3);
            } else {
                v0 *= scale; v1 *= scale; v2 *= scale; v3 *= scale;
                if (mode == 2) {
                    float r0, r1, r2, r3;
                    uint32_t h01 = packh2_res(v0, v1, r0, r1);
                    uint32_t h23 = packh2_res(v2, v3, r2, r3);
                    *(uint32_t*)((__half*)O1 + p0) = h01;
                    *(uint32_t*)((__half*)O1 + p1) = h23;
                    *(uint32_t*)((__half*)O2 + p0) = packh2(r0, r1);
                    *(uint32_t*)((__half*)O2 + p1) = packh2(r2, r3);
                } else {  // mode 3: fp16 single
                    *(uint32_t*)((__half*)O1 + p0) = packh2(v0, v1);
                    *(uint32_t*)((__half*)O1 + p1) = packh2(v2, v3);
                }
            }
        }
    }
}

// ================================================================================
// Flash attention via mma.sync, fp16: Q single, K hi/lo, V hi/lo, P single.
// CTA: 128 q-rows x one (b,h); 8 warps, each m16 x n64 fragments.
// KV tiles of 64, cp.async double-buffered. Causal tile-skip + diagonal mask.
// smem: Q 16KB + 2 x (Kh,Kl,Vh,Vl 8KB ea) = 80KB
// ================================================================================
#define ATT_SMEM 81920

__global__ __launch_bounds__(256) void attn_mma_kernel(
    const __half* __restrict__ qh,
    const __half* __restrict__ kh, const __half* __restrict__ kl,
    const __half* __restrict__ vh, const __half* __restrict__ vl,
    __half* __restrict__ yh, __half* __restrict__ yl)
{
    extern __shared__ char smem[];
    const uint32_t sb = smem_u32(smem);
    const uint32_t sQ = sb;
    const uint32_t sKV = sb + 16384;   // + buf*32768: Kh@0, Kl@8K, Vh@16K, Vl@24K

    const int tid = threadIdx.x;
    const int wid = tid >> 5;
    const int lane = tid & 31;
    const int lrow = (lane & 7) + ((lane >> 3) & 1) * 8;
    const int lkb = (lane >> 4) * 16;

    const int q0 = blockIdx.x * 128;
    const int bh = blockIdx.y;
    const int b = bh >> 4;
    const int h = bh & 15;
    const size_t base = (size_t)b * TT * CC + (size_t)h * HD;

    // Q tile load (single fp16): 128 rows x 128B
#pragma unroll
    for (int f = tid; f < 1024; f += 256) {
        int row = f >> 3, c16 = f & 7;
        cp16(sQ + SWZ(row, c16 * 16), qh + base + (size_t)(q0 + row) * CC + c16 * 8);
    }

    const __half* kvsrc[4] = {kh, kl, vh, vl};
    auto load_kv = [&](int kt, int buf) {
        const uint32_t db = sKV + buf * 32768;
#pragma unroll
        for (int f = tid; f < 2048; f += 256) {
            int mat = f >> 9, idx = f & 511;
            int row = idx >> 3, c16 = idx & 7;
            cp16(db + mat * 8192 + SWZ(row, c16 * 16),
                 kvsrc[mat] + base + (size_t)(kt * 64 + row) * CC + c16 * 8);
        }
    };

    const int nkt = 2 * (blockIdx.x + 1);
    load_kv(0, 0);
    CP_COMMIT();

    float m0 = -3.0e38f, m1 = -3.0e38f, l0 = 0.0f, l1 = 0.0f;
    float o[8][4];
#pragma unroll
    for (int nt = 0; nt < 8; nt++)
#pragma unroll
        for (int c = 0; c < 4; c++) o[nt][c] = 0.0f;

    const int q0w = q0 + 16 * wid;

    for (int kt = 0; kt < nkt; kt++) {
        const int buf = kt & 1;
        if (kt + 1 < nkt) {
            load_kv(kt + 1, buf ^ 1);
            CP_COMMIT();
            CP_WAIT(1);
        } else {
            CP_WAIT(0);
        }
        __syncthreads();

        const int kc = kt * 64;
        if (kc <= q0w + 15) {   // not fully masked for this warp
            const uint32_t bK = sKV + buf * 32768;
            const uint32_t bKl = bK + 8192;
            const uint32_t bV = bK + 16384;
            const uint32_t bVl = bK + 24576;

            // ---- S = Q K^T (Q single fp16, K fp16 hi+lo) ----
            float s[8][4];
#pragma unroll
            for (int nt = 0; nt < 8; nt++)
#pragma unroll
                for (int c = 0; c < 4; c++) s[nt][c] = 0.0f;

#pragma unroll
            for (int ks = 0; ks < 4; ks++) {
                const int kb = ks * 32;
                uint32_t a[4];
                ldm_x4(a, sQ + SWZ(16 * wid + lrow, kb + lkb));
#pragma unroll
                for (int nt2 = 0; nt2 < 4; nt2++) {
                    uint32_t boff = SWZ(nt2 * 16 + lrow, kb + lkb);
                    uint32_t bhf[4], blf[4];
                    ldm_x4(bhf, bK + boff);
                    ldm_x4(blf, bKl + boff);
#pragma unroll
                    for (int hh = 0; hh < 2; hh++) {
                        int nt = nt2 * 2 + hh;
                        mma_f16(s[nt], a, bhf[hh], bhf[hh + 2]);
                        mma_f16(s[nt], a, blf[hh], blf[hh + 2]);
                    }
                }
            }

            // ---- causal mask on diagonal tiles ----
            if (kc + 63 > q0w) {
                const int r0 = q0w + (lane >> 2);
                const int r1 = r0 + 8;
#pragma unroll
                for (int nt = 0; nt < 8; nt++) {
                    int c0 = kc + 8 * nt + 2 * (lane & 3);
                    if (c0 > r0)     s[nt][0] = -1.0e30f;
                    if (c0 + 1 > r0) s[nt][1] = -1.0e30f;
                    if (c0 > r1)     s[nt][2] = -1.0e30f;
                    if (c0 + 1 > r1) s[nt][3] = -1.0e30f;
                }
            }

            // ---- online softmax ----
            float mt0 = -3.0e38f, mt1 = -3.0e38f;
#pragma unroll
            for (int nt = 0; nt < 8; nt++) {
                mt0 = fmaxf(mt0, fmaxf(s[nt][0], s[nt][1]));
                mt1 = fmaxf(mt1, fmaxf(s[nt][2], s[nt][3]));
            }
#pragma unroll
            for (int d = 1; d <= 2; d <<= 1) {
                mt0 = fmaxf(mt0, __shfl_xor_sync(0xffffffffu, mt0, d));
                mt1 = fmaxf(mt1, __shfl_xor_sync(0xffffffffu, mt1, d));
            }
            float mn0 = fmaxf(m0, mt0), mn1 = fmaxf(m1, mt1);
            float corr0 = __expf(m0 - mn0), corr1 = __expf(m1 - mn1);
            float ls0 = 0.0f, ls1 = 0.0f;
#pragma unroll
            for (int nt = 0; nt < 8; nt++) {
                s[nt][0] = __expf(s[nt][0] - mn0);
                s[nt][1] = __expf(s[nt][1] - mn0);
                s[nt][2] = __expf(s[nt][2] - mn1);
                s[nt][3] = __expf(s[nt][3] - mn1);
                ls0 += s[nt][0] + s[nt][1];
                ls1 += s[nt][2] + s[nt][3];
            }
#pragma unroll
            for (int d = 1; d <= 2; d <<= 1) {
                ls0 += __shfl_xor_sync(0xffffffffu, ls0, d);
                ls1 += __shfl_xor_sync(0xffffffffu, ls1, d);
            }
            l0 = l0 * corr0 + ls0;  m0 = mn0;
            l1 = l1 * corr1 + ls1;  m1 = mn1;
#pragma unroll
            for (int nt = 0; nt < 8; nt++) {
                o[nt][0] *= corr0; o[nt][1] *= corr0;
                o[nt][2] *= corr1; o[nt][3] *= corr1;
            }

            // ---- O += P V (P single fp16, V fp16 hi+lo) ----
#pragma unroll
            for (int ks = 0; ks < 4; ks++) {
                uint32_t a[4];
                a[0] = packh2(s[2 * ks][0], s[2 * ks][1]);
                a[1] = packh2(s[2 * ks][2], s[2 * ks][3]);
                a[2] = packh2(s[2 * ks + 1][0], s[2 * ks + 1][1]);
                a[3] = packh2(s[2 * ks + 1][2], s[2 * ks + 1][3]);
#pragma unroll
                for (int nt2 = 0; nt2 < 4; nt2++) {
                    uint32_t voff = SWZ(ks * 16 + lrow, nt2 * 32 + lkb);
                    uint32_t bvh[4], bvl[4];
                    ldm_x4_t(bvh, bV + voff);
                    ldm_x4_t(bvl, bVl + voff);
#pragma unroll
                    for (int hh = 0; hh < 2; hh++) {
                        int nt = nt2 * 2 + hh;
                        mma_f16(o[nt], a, bvh[2 * hh], bvh[2 * hh + 1]);
                        mma_f16(o[nt], a, bvl[2 * hh], bvl[2 * hh + 1]);
                    }
                }
            }
        }
        __syncthreads();
    }

    // ---- normalize, split fp16 hi/lo, store ----
    const float inv0 = 1.0f / l0, inv1 = 1.0f / l1;
    const int t0 = q0w + (lane >> 2);
    const int t1 = t0 + 8;
#pragma unroll
    for (int nt = 0; nt < 8; nt++) {
        const int c = 8 * nt + 2 * (lane & 3);
        const size_t o0 = base + (size_t)t0 * CC + c;
        const size_t o1 = base + (size_t)t1 * CC + c;
        float v0 = o[nt][0] * inv0, v1 = o[nt][1] * inv0;
        float v2 = o[nt][2] * inv1, v3 = o[nt][3] * inv1;
        float r0, r1, r2, r3;
        uint32_t h01 = packh2_res(v0, v1, r0, r1);
        uint32_t h23 = packh2_res(v2, v3, r2, r3);
        *(uint32_t*)&yh[o0] = h01;
        *(uint32_t*)&yh[o1] = h23;
        *(uint32_t*)&yl[o0] = packh2(r0, r1);
        *(uint32_t*)&yl[o1] = packh2(r2, r3);
    }
}

// ================================================================================
// launch
// ================================================================================
extern "C" void kernel_launch(void* const* d_in, const int* in_sizes, int n_in,
                              void* d_out, int out_size)
{
    const float* x  = (const float*)d_in[0];
    const float* Wq = (const float*)d_in[1];
    const float* bq = (const float*)d_in[2];
    const float* Wk = (const float*)d_in[3];
    const float* bk = (const float*)d_in[4];
    const float* Wv = (const float*)d_in[5];
    const float* bv = (const float*)d_in[6];
    const float* Wp = (const float*)d_in[7];
    float* out = (float*)d_out;

    __half *xh, *xl, *qh, *kh, *kl, *vh, *vl, *yh, *yl, *w;
    cudaGetSymbolAddress((void**)&xh, g_xh);
    cudaGetSymbolAddress((void**)&xl, g_xl);
    cudaGetSymbolAddress((void**)&qh, g_qh);
    cudaGetSymbolAddress((void**)&kh, g_kh);
    cudaGetSymbolAddress((void**)&kl, g_kl);
    cudaGetSymbolAddress((void**)&vh, g_vh);
    cudaGetSymbolAddress((void**)&vl, g_vl);
    cudaGetSymbolAddress((void**)&yh, g_yh);
    cudaGetSymbolAddress((void**)&yl, g_yl);
    cudaGetSymbolAddress((void**)&w,  g_w);

    const int WSZ = CC * CC;

    cudaFuncSetAttribute(gemm_mma_kernel, cudaFuncAttributeMaxDynamicSharedMemorySize,
                         SMEM_GEMM);
    cudaFuncSetAttribute(attn_mma_kernel, cudaFuncAttributeMaxDynamicSharedMemorySize,
                         ATT_SMEM);

    // splits: x -> fp16 hi/lo; weights -> fp16 single
    split_h_kernel<<<ELEMS / 4 / 256, 256>>>(x, xh, xl, ELEMS / 4);
    conv_h_kernel<<<WSZ / 4 / 256, 256>>>(Wq, w + 0 * WSZ, WSZ / 4);
    conv_h_kernel<<<WSZ / 4 / 256, 256>>>(Wk, w + 1 * WSZ, WSZ / 4);
    conv_h_kernel<<<WSZ / 4 / 256, 256>>>(Wv, w + 2 * WSZ, WSZ / 4);
    conv_h_kernel<<<WSZ / 4 / 256, 256>>>(Wp, w + 3 * WSZ, WSZ / 4);

    dim3 gg(CC / 128, MM / 128);  // (8, 64)
    // Q -> fp16 single (pre-scaled by 1/sqrt(HD)); K,V -> fp16 hi/lo
    gemm_mma_kernel<<<gg, 256, SMEM_GEMM>>>(xh, xl, w + 0 * WSZ, bq,
                                            nullptr, qh, nullptr, 0.125f, 3);
    gemm_mma_kernel<<<gg, 256, SMEM_GEMM>>>(xh, xl, w + 1 * WSZ, bk,
                                            nullptr, kh, kl, 1.0f, 2);
    gemm_mma_kernel<<<gg, 256, SMEM_GEMM>>>(xh, xl, w + 2 * WSZ, bv,
                                            nullptr, vh, vl, 1.0f, 2);

    // attention (tensor-core fp16, 2+2 MMA terms)
    attn_mma_kernel<<<dim3(TT / 128, BB * HH), 256, ATT_SMEM>>>(qh, kh, kl,
                                                                vh, vl, yh, yl);

    // output projection -> fp32 out
    gemm_mma_kernel<<<gg, 256, SMEM_GEMM>>>(yh, yl, w + 3 * WSZ,
                                            nullptr, out, nullptr, nullptr, 1.0f, 0);
}

// round 7
// speedup vs baseline: 7.1172x; 1.5520x over previous
#include <cuda_runtime.h>
#include <cuda_bf16.h>
#include <cuda_fp16.h>
#include <cstdint>
#include <cstddef>

// Problem constants
#define BB 4
#define TT 2048
#define CC 1024
#define HH 16
#define HD 64
#define MM (BB * TT)          // 8192 rows

// ---------------- scratch (static device globals; no allocation) ----------------
#define ELEMS (BB * TT * CC)  // 8,388,608
__device__ __half g_xh[ELEMS];        // x: single fp16
__device__ __half g_qh[ELEMS];        // Q: single fp16 (pre-scaled)
__device__ __half g_kh[ELEMS];        // K: single fp16
__device__ __half g_vh[ELEMS];        // V: single fp16
__device__ __half g_yh[ELEMS];        // attention out hi
__device__ __half g_yl[ELEMS];        // attention out lo
__device__ __half g_w[4 * CC * CC];   // weights: single fp16

// ================================================================================
// PTX helpers (base sm_103-safe: mma.sync / ldmatrix / cp.async only)
// ================================================================================
__device__ __forceinline__ uint32_t smem_u32(const void* p) {
    uint32_t a;
    asm("{ .reg .u64 t; cvta.to.shared.u64 t, %1; cvt.u32.u64 %0, t; }" : "=r"(a) : "l"(p));
    return a;
}

__device__ __forceinline__ void cp16(uint32_t dst, const void* src) {
    asm volatile("cp.async.cg.shared.global [%0], [%1], 16;" :: "r"(dst), "l"(src));
}
#define CP_COMMIT() asm volatile("cp.async.commit_group;" ::: "memory")
#define CP_WAIT(n)  asm volatile("cp.async.wait_group %0;" :: "n"(n) : "memory")

__device__ __forceinline__ void ldm_x4(uint32_t* r, uint32_t addr) {
    asm volatile("ldmatrix.sync.aligned.m8n8.x4.shared.b16 {%0,%1,%2,%3}, [%4];"
        : "=r"(r[0]), "=r"(r[1]), "=r"(r[2]), "=r"(r[3]) : "r"(addr));
}
__device__ __forceinline__ void ldm_x4_t(uint32_t* r, uint32_t addr) {
    asm volatile("ldmatrix.sync.aligned.m8n8.x4.trans.shared.b16 {%0,%1,%2,%3}, [%4];"
        : "=r"(r[0]), "=r"(r[1]), "=r"(r[2]), "=r"(r[3]) : "r"(addr));
}

__device__ __forceinline__ void mma_f16(float* d, const uint32_t* a,
                                        uint32_t b0, uint32_t b1) {
    asm volatile(
        "mma.sync.aligned.m16n8k16.row.col.f32.f16.f16.f32 "
        "{%0,%1,%2,%3}, {%4,%5,%6,%7}, {%8,%9}, {%0,%1,%2,%3};"
        : "+f"(d[0]), "+f"(d[1]), "+f"(d[2]), "+f"(d[3])
        : "r"(a[0]), "r"(a[1]), "r"(a[2]), "r"(a[3]), "r"(b0), "r"(b1));
}

// SW128 swizzle on a 128B-row tile
#define SWZ(row, kbyte) (((row) << 7) + ((kbyte) ^ (((row) & 7) << 4)))

// fp16 pack helpers
__device__ __forceinline__ uint32_t packh2(float x, float y) {
    __half2 p = __floats2half2_rn(x, y);
    return *reinterpret_cast<uint32_t*>(&p);
}
__device__ __forceinline__ uint32_t packh2_res(float x, float y, float& rx, float& ry) {
    __half hx = __float2half_rn(x), hy = __float2half_rn(y);
    rx = x - __half2float(hx);
    ry = y - __half2float(hy);
    __half2 p(hx, hy);
    return *reinterpret_cast<uint32_t*>(&p);
}

// ================================================================================
// fp32 -> fp16 single (x and weights)
// ================================================================================
__global__ __launch_bounds__(256) void conv_h_kernel(
    const float* __restrict__ src, __half* __restrict__ dst, int n4)
{
    int i = blockIdx.x * 256 + threadIdx.x;
    if (i >= n4) return;
    float4 v = ((const float4*)src)[i];
    ((uint32_t*)dst)[2 * i + 0] = packh2(v.x, v.y);
    ((uint32_t*)dst)[2 * i + 1] = packh2(v.z, v.w);
}

// ================================================================================
// fp16 mma.sync GEMM, TERMS = 1 or 2 A-operand terms:
//   C[M,N] = (Ah [+ Al])[M,K] @ W[N,K]^T (+bias)
// 128x128 tile/CTA, 8 warps (2m x 4n), K-chunk 64, cp.async double-buffered.
// Epilogue modes: 0 = fp32 -> Cf;  3 = fp16 single -> O1 (scaled).
// ================================================================================
#define KC 64
#define NCHUNK (CC / KC)      // 16
#define TILE_B 16384          // 128 rows x 128B (64 fp16)

template<int TERMS>
__global__ __launch_bounds__(256) void gemm_mma_kernel(
    const __half* __restrict__ Ah, const __half* __restrict__ Al,
    const __half* __restrict__ B,
    const float* __restrict__ bias, float* __restrict__ Cf,
    __half* __restrict__ O1, float scale, int mode)
{
    constexpr int NPART = TERMS + 1;
    constexpr int BUF_B = NPART * TILE_B;

    extern __shared__ char smem[];
    const uint32_t sbase = smem_u32(smem);
    const int tid = threadIdx.x;
    const int wid = tid >> 5;
    const int lane = tid & 31;
    const int wm = wid & 1;
    const int wn = wid >> 1;
    const int bm = blockIdx.y * 128;
    const int bn = blockIdx.x * 128;

    const __half* srcs[3] = {Ah, (TERMS == 2) ? Al : B, B};

    const int lrow = (lane & 7) + ((lane >> 3) & 1) * 8;
    const int lkb = (lane >> 4) * 16;

    float acc[4][4][4];
#pragma unroll
    for (int a = 0; a < 4; a++)
#pragma unroll
        for (int b = 0; b < 4; b++)
#pragma unroll
            for (int c = 0; c < 4; c++) acc[a][b][c] = 0.0f;

    auto load_chunk = [&](int chunk, int buf) {
        const int k0 = chunk * KC;
        const uint32_t tbu = sbase + buf * BUF_B;
#pragma unroll
        for (int part = 0; part < NPART; part++) {
            const __half* p = srcs[part];
            const int roff = (part < TERMS) ? bm : bn;
            const uint32_t db = tbu + part * TILE_B;
#pragma unroll
            for (int f = tid; f < 1024; f += 256) {
                int row = f >> 3;
                int c16 = f & 7;
                cp16(db + SWZ(row, c16 * 16),
                     p + (size_t)(roff + row) * CC + k0 + c16 * 8);
            }
        }
        CP_COMMIT();
    };

    load_chunk(0, 0);

    for (int chunk = 0; chunk < NCHUNK; chunk++) {
        const int buf = chunk & 1;
        if (chunk + 1 < NCHUNK) {
            load_chunk(chunk + 1, buf ^ 1);
            CP_WAIT(1);
        } else {
            CP_WAIT(0);
        }
        __syncthreads();

        const uint32_t tAh = sbase + buf * BUF_B;
        const uint32_t tAl = tAh + TILE_B;                 // valid only if TERMS==2
        const uint32_t tB  = tAh + TERMS * TILE_B;

#pragma unroll
        for (int ks = 0; ks < 4; ks++) {
            const int kb = ks * 32;
            uint32_t ah[4][4], al[4][4], bf[2][4];
#pragma unroll
            for (int mi = 0; mi < 4; mi++) {
                int row = wm * 64 + mi * 16 + lrow;
                uint32_t off = SWZ(row, kb + lkb);
                ldm_x4(ah[mi], tAh + off);
                if (TERMS == 2) ldm_x4(al[mi], tAl + off);
            }
#pragma unroll
            for (int nj2 = 0; nj2 < 2; nj2++) {
                int row = wn * 32 + nj2 * 16 + lrow;
                ldm_x4(bf[nj2], tB + SWZ(row, kb + lkb));
            }
#pragma unroll
            for (int mi = 0; mi < 4; mi++) {
#pragma unroll
                for (int nj = 0; nj < 4; nj++) {
                    const int h = nj & 1;
                    mma_f16(acc[mi][nj], ah[mi], bf[nj >> 1][h], bf[nj >> 1][h + 2]);
                    if (TERMS == 2)
                        mma_f16(acc[mi][nj], al[mi], bf[nj >> 1][h], bf[nj >> 1][h + 2]);
                }
            }
        }
        __syncthreads();
    }

    // epilogue
    const int lr = lane >> 2;
    const int lc = (lane & 3) * 2;
#pragma unroll
    for (int nj = 0; nj < 4; nj++) {
        const int c = bn + wn * 32 + nj * 8 + lc;
        float b0 = 0.0f, b1 = 0.0f;
        if (bias) { b0 = bias[c]; b1 = bias[c + 1]; }
#pragma unroll
        for (int mi = 0; mi < 4; mi++) {
            const int r = bm + wm * 64 + mi * 16 + lr;
            float v0 = acc[mi][nj][0] + b0, v1 = acc[mi][nj][1] + b1;
            float v2 = acc[mi][nj][2] + b0, v3 = acc[mi][nj][3] + b1;
            const size_t p0 = (size_t)r * CC + c;
            const size_t p1 = (size_t)(r + 8) * CC + c;
            if (mode == 0) {
                *(float2*)&Cf[p0] = make_float2(v0, v1);
                *(float2*)&Cf[p1] = make_float2(v2, v3);
            } else {  // mode 3: fp16 single, scaled
                *(uint32_t*)&O1[p0] = packh2(v0 * scale, v1 * scale);
                *(uint32_t*)&O1[p1] = packh2(v2 * scale, v3 * scale);
            }
        }
    }
}

// ================================================================================
// Flash attention via mma.sync, all-single fp16 operands (Q, K, V, P).
// CTA: 128 q-rows x one (b,h); 8 warps, each m16 x n64 fragments.
// KV tiles of 64, cp.async double-buffered. Causal tile-skip + diagonal mask.
// smem: Q 16KB + 2 x (K 8KB + V 8KB) = 48KB
// ================================================================================
#define ATT_SMEM 49152

__global__ __launch_bounds__(256) void attn_mma_kernel(
    const __half* __restrict__ qh, const __half* __restrict__ kh,
    const __half* __restrict__ vh,
    __half* __restrict__ yh, __half* __restrict__ yl)
{
    extern __shared__ char smem[];
    const uint32_t sb = smem_u32(smem);
    const uint32_t sQ = sb;
    const uint32_t sKV = sb + 16384;   // + buf*16384: K@0, V@8192

    const int tid = threadIdx.x;
    const int wid = tid >> 5;
    const int lane = tid & 31;
    const int lrow = (lane & 7) + ((lane >> 3) & 1) * 8;
    const int lkb = (lane >> 4) * 16;

    const int q0 = blockIdx.x * 128;
    const int bh = blockIdx.y;
    const int b = bh >> 4;
    const int h = bh & 15;
    const size_t base = (size_t)b * TT * CC + (size_t)h * HD;

    // Q tile load (single fp16): 128 rows x 128B
#pragma unroll
    for (int f = tid; f < 1024; f += 256) {
        int row = f >> 3, c16 = f & 7;
        cp16(sQ + SWZ(row, c16 * 16), qh + base + (size_t)(q0 + row) * CC + c16 * 8);
    }

    const __half* kvsrc[2] = {kh, vh};
    auto load_kv = [&](int kt, int buf) {
        const uint32_t db = sKV + buf * 16384;
#pragma unroll
        for (int f = tid; f < 1024; f += 256) {
            int mat = f >> 9, idx = f & 511;
            int row = idx >> 3, c16 = idx & 7;
            cp16(db + mat * 8192 + SWZ(row, c16 * 16),
                 kvsrc[mat] + base + (size_t)(kt * 64 + row) * CC + c16 * 8);
        }
    };

    const int nkt = 2 * (blockIdx.x + 1);
    load_kv(0, 0);
    CP_COMMIT();

    float m0 = -3.0e38f, m1 = -3.0e38f, l0 = 0.0f, l1 = 0.0f;
    float o[8][4];
#pragma unroll
    for (int nt = 0; nt < 8; nt++)
#pragma unroll
        for (int c = 0; c < 4; c++) o[nt][c] = 0.0f;

    const int q0w = q0 + 16 * wid;

    for (int kt = 0; kt < nkt; kt++) {
        const int buf = kt & 1;
        if (kt + 1 < nkt) {
            load_kv(kt + 1, buf ^ 1);
            CP_COMMIT();
            CP_WAIT(1);
        } else {
            CP_WAIT(0);
        }
        __syncthreads();

        const int kc = kt * 64;
        if (kc <= q0w + 15) {   // not fully masked for this warp
            const uint32_t bK = sKV + buf * 16384;
            const uint32_t bV = bK + 8192;

            // ---- S = Q K^T (single fp16) ----
            float s[8][4];
#pragma unroll
            for (int nt = 0; nt < 8; nt++)
#pragma unroll
                for (int c = 0; c < 4; c++) s[nt][c] = 0.0f;

#pragma unroll
            for (int ks = 0; ks < 4; ks++) {
                const int kb = ks * 32;
                uint32_t a[4];
                ldm_x4(a, sQ + SWZ(16 * wid + lrow, kb + lkb));
#pragma unroll
                for (int nt2 = 0; nt2 < 4; nt2++) {
                    uint32_t bhf[4];
                    ldm_x4(bhf, bK + SWZ(nt2 * 16 + lrow, kb + lkb));
#pragma unroll
                    for (int hh = 0; hh < 2; hh++) {
                        mma_f16(s[nt2 * 2 + hh], a, bhf[hh], bhf[hh + 2]);
                    }
                }
            }

            // ---- causal mask on diagonal tiles ----
            if (kc + 63 > q0w) {
                const int r0 = q0w + (lane >> 2);
                const int r1 = r0 + 8;
#pragma unroll
                for (int nt = 0; nt < 8; nt++) {
                    int c0 = kc + 8 * nt + 2 * (lane & 3);
                    if (c0 > r0)     s[nt][0] = -1.0e30f;
                    if (c0 + 1 > r0) s[nt][1] = -1.0e30f;
                    if (c0 > r1)     s[nt][2] = -1.0e30f;
                    if (c0 + 1 > r1) s[nt][3] = -1.0e30f;
                }
            }

            // ---- online softmax ----
            float mt0 = -3.0e38f, mt1 = -3.0e38f;
#pragma unroll
            for (int nt = 0; nt < 8; nt++) {
                mt0 = fmaxf(mt0, fmaxf(s[nt][0], s[nt][1]));
                mt1 = fmaxf(mt1, fmaxf(s[nt][2], s[nt][3]));
            }
#pragma unroll
            for (int d = 1; d <= 2; d <<= 1) {
                mt0 = fmaxf(mt0, __shfl_xor_sync(0xffffffffu, mt0, d));
                mt1 = fmaxf(mt1, __shfl_xor_sync(0xffffffffu, mt1, d));
            }
            float mn0 = fmaxf(m0, mt0), mn1 = fmaxf(m1, mt1);
            float corr0 = __expf(m0 - mn0), corr1 = __expf(m1 - mn1);
            float ls0 = 0.0f, ls1 = 0.0f;
#pragma unroll
            for (int nt = 0; nt < 8; nt++) {
                s[nt][0] = __expf(s[nt][0] - mn0);
                s[nt][1] = __expf(s[nt][1] - mn0);
                s[nt][2] = __expf(s[nt][2] - mn1);
                s[nt][3] = __expf(s[nt][3] - mn1);
                ls0 += s[nt][0] + s[nt][1];
                ls1 += s[nt][2] + s[nt][3];
            }
#pragma unroll
            for (int d = 1; d <= 2; d <<= 1) {
                ls0 += __shfl_xor_sync(0xffffffffu, ls0, d);
                ls1 += __shfl_xor_sync(0xffffffffu, ls1, d);
            }
            l0 = l0 * corr0 + ls0;  m0 = mn0;
            l1 = l1 * corr1 + ls1;  m1 = mn1;
#pragma unroll
            for (int nt = 0; nt < 8; nt++) {
                o[nt][0] *= corr0; o[nt][1] *= corr0;
                o[nt][2] *= corr1; o[nt][3] *= corr1;
            }

            // ---- O += P V (single fp16) ----
#pragma unroll
            for (int ks = 0; ks < 4; ks++) {
                uint32_t a[4];
                a[0] = packh2(s[2 * ks][0], s[2 * ks][1]);
                a[1] = packh2(s[2 * ks][2], s[2 * ks][3]);
                a[2] = packh2(s[2 * ks + 1][0], s[2 * ks + 1][1]);
                a[3] = packh2(s[2 * ks + 1][2], s[2 * ks + 1][3]);
#pragma unroll
                for (int nt2 = 0; nt2 < 4; nt2++) {
                    uint32_t bvh[4];
                    ldm_x4_t(bvh, bV + SWZ(ks * 16 + lrow, nt2 * 32 + lkb));
#pragma unroll
                    for (int hh = 0; hh < 2; hh++) {
                        mma_f16(o[nt2 * 2 + hh], a, bvh[2 * hh], bvh[2 * hh + 1]);
                    }
                }
            }
        }
        __syncthreads();
    }

    // ---- normalize, split fp16 hi/lo, store ----
    const float inv0 = 1.0f / l0, inv1 = 1.0f / l1;
    const int t0 = q0w + (lane >> 2);
    const int t1 = t0 + 8;
#pragma unroll
    for (int nt = 0; nt < 8; nt++) {
        const int c = 8 * nt + 2 * (lane & 3);
        const size_t o0 = base + (size_t)t0 * CC + c;
        const size_t o1 = base + (size_t)t1 * CC + c;
        float v0 = o[nt][0] * inv0, v1 = o[nt][1] * inv0;
        float v2 = o[nt][2] * inv1, v3 = o[nt][3] * inv1;
        float r0, r1, r2, r3;
        uint32_t h01 = packh2_res(v0, v1, r0, r1);
        uint32_t h23 = packh2_res(v2, v3, r2, r3);
        *(uint32_t*)&yh[o0] = h01;
        *(uint32_t*)&yh[o1] = h23;
        *(uint32_t*)&yl[o0] = packh2(r0, r1);
        *(uint32_t*)&yl[o1] = packh2(r2, r3);
    }
}

// ================================================================================
// launch
// ================================================================================
extern "C" void kernel_launch(void* const* d_in, const int* in_sizes, int n_in,
                              void* d_out, int out_size)
{
    const float* x  = (const float*)d_in[0];
    const float* Wq = (const float*)d_in[1];
    const float* bq = (const float*)d_in[2];
    const float* Wk = (const float*)d_in[3];
    const float* bk = (const float*)d_in[4];
    const float* Wv = (const float*)d_in[5];
    const float* bv = (const float*)d_in[6];
    const float* Wp = (const float*)d_in[7];
    float* out = (float*)d_out;

    __half *xh, *qh, *kh, *vh, *yh, *yl, *w;
    cudaGetSymbolAddress((void**)&xh, g_xh);
    cudaGetSymbolAddress((void**)&qh, g_qh);
    cudaGetSymbolAddress((void**)&kh, g_kh);
    cudaGetSymbolAddress((void**)&vh, g_vh);
    cudaGetSymbolAddress((void**)&yh, g_yh);
    cudaGetSymbolAddress((void**)&yl, g_yl);
    cudaGetSymbolAddress((void**)&w,  g_w);

    const int WSZ = CC * CC;

    const int smem_g1 = 2 * 2 * TILE_B;   // 65536
    const int smem_g2 = 2 * 3 * TILE_B;   // 98304
    cudaFuncSetAttribute(gemm_mma_kernel<1>, cudaFuncAttributeMaxDynamicSharedMemorySize,
                         smem_g1);
    cudaFuncSetAttribute(gemm_mma_kernel<2>, cudaFuncAttributeMaxDynamicSharedMemorySize,
                         smem_g2);
    cudaFuncSetAttribute(attn_mma_kernel, cudaFuncAttributeMaxDynamicSharedMemorySize,
                         ATT_SMEM);

    // conversions: x and weights -> single fp16
    conv_h_kernel<<<ELEMS / 4 / 256, 256>>>(x, xh, ELEMS / 4);
    conv_h_kernel<<<WSZ / 4 / 256, 256>>>(Wq, w + 0 * WSZ, WSZ / 4);
    conv_h_kernel<<<WSZ / 4 / 256, 256>>>(Wk, w + 1 * WSZ, WSZ / 4);
    conv_h_kernel<<<WSZ / 4 / 256, 256>>>(Wv, w + 2 * WSZ, WSZ / 4);
    conv_h_kernel<<<WSZ / 4 / 256, 256>>>(Wp, w + 3 * WSZ, WSZ / 4);

    dim3 gg(CC / 128, MM / 128);  // (8, 64)
    // QKV projections: 1-term fp16, single fp16 out (Q pre-scaled by 1/sqrt(HD))
    gemm_mma_kernel<1><<<gg, 256, smem_g1>>>(xh, nullptr, w + 0 * WSZ, bq,
                                             nullptr, qh, 0.125f, 3);
    gemm_mma_kernel<1><<<gg, 256, smem_g1>>>(xh, nullptr, w + 1 * WSZ, bk,
                                             nullptr, kh, 1.0f, 3);
    gemm_mma_kernel<1><<<gg, 256, smem_g1>>>(xh, nullptr, w + 2 * WSZ, bv,
                                             nullptr, vh, 1.0f, 3);

    // attention (tensor-core fp16, 1+1 MMA terms)
    attn_mma_kernel<<<dim3(TT / 128, BB * HH), 256, ATT_SMEM>>>(qh, kh, vh, yh, yl);

    // output projection: 2-term (yh+yl)·Wp -> fp32 out
    gemm_mma_kernel<2><<<gg, 256, smem_g2>>>(yh, yl, w + 3 * WSZ,
                                             nullptr, out, nullptr, 1.0f, 0);
}

// round 8
// speedup vs baseline: 7.5133x; 1.0557x over previous
#include <cuda_runtime.h>
#include <cuda_bf16.h>
#include <cuda_fp16.h>
#include <cstdint>
#include <cstddef>

// Problem constants
#define BB 4
#define TT 2048
#define CC 1024
#define HH 16
#define HD 64
#define MM (BB * TT)          // 8192 rows

// ---------------- scratch (static device globals; no allocation) ----------------
#define ELEMS (BB * TT * CC)  // 8,388,608
__device__ __half g_xh[ELEMS];        // x: single fp16
__device__ __half g_qh[ELEMS];        // Q: single fp16 (pre-scaled)
__device__ __half g_kh[ELEMS];        // K: single fp16
__device__ __half g_vh[ELEMS];        // V: single fp16
__device__ __half g_yh[ELEMS];        // attention out hi
__device__ __half g_yl[ELEMS];        // attention out lo
__device__ __half g_w[4 * CC * CC];   // weights: single fp16

// ================================================================================
// PTX helpers (base sm_103-safe: mma.sync / ldmatrix / cp.async only)
// ================================================================================
__device__ __forceinline__ uint32_t smem_u32(const void* p) {
    uint32_t a;
    asm("{ .reg .u64 t; cvta.to.shared.u64 t, %1; cvt.u32.u64 %0, t; }" : "=r"(a) : "l"(p));
    return a;
}

__device__ __forceinline__ void cp16(uint32_t dst, const void* src) {
    asm volatile("cp.async.cg.shared.global [%0], [%1], 16;" :: "r"(dst), "l"(src));
}
#define CP_COMMIT() asm volatile("cp.async.commit_group;" ::: "memory")
#define CP_WAIT(n)  asm volatile("cp.async.wait_group %0;" :: "n"(n) : "memory")

__device__ __forceinline__ void ldm_x4(uint32_t* r, uint32_t addr) {
    asm volatile("ldmatrix.sync.aligned.m8n8.x4.shared.b16 {%0,%1,%2,%3}, [%4];"
        : "=r"(r[0]), "=r"(r[1]), "=r"(r[2]), "=r"(r[3]) : "r"(addr));
}
__device__ __forceinline__ void ldm_x4_t(uint32_t* r, uint32_t addr) {
    asm volatile("ldmatrix.sync.aligned.m8n8.x4.trans.shared.b16 {%0,%1,%2,%3}, [%4];"
        : "=r"(r[0]), "=r"(r[1]), "=r"(r[2]), "=r"(r[3]) : "r"(addr));
}

__device__ __forceinline__ void mma_f16(float* d, const uint32_t* a,
                                        uint32_t b0, uint32_t b1) {
    asm volatile(
        "mma.sync.aligned.m16n8k16.row.col.f32.f16.f16.f32 "
        "{%0,%1,%2,%3}, {%4,%5,%6,%7}, {%8,%9}, {%0,%1,%2,%3};"
        : "+f"(d[0]), "+f"(d[1]), "+f"(d[2]), "+f"(d[3])
        : "r"(a[0]), "r"(a[1]), "r"(a[2]), "r"(a[3]), "r"(b0), "r"(b1));
}

// SW128 swizzle on a 128B-row tile
#define SWZ(row, kbyte) (((row) << 7) + ((kbyte) ^ (((row) & 7) << 4)))

// fp16 pack helpers
__device__ __forceinline__ uint32_t packh2(float x, float y) {
    __half2 p = __floats2half2_rn(x, y);
    return *reinterpret_cast<uint32_t*>(&p);
}
__device__ __forceinline__ uint32_t packh2_res(float x, float y, float& rx, float& ry) {
    __half hx = __float2half_rn(x), hy = __float2half_rn(y);
    rx = x - __half2float(hx);
    ry = y - __half2float(hy);
    __half2 p(hx, hy);
    return *reinterpret_cast<uint32_t*>(&p);
}

// ================================================================================
// fp32 -> fp16 single conversions
// ================================================================================
__global__ __launch_bounds__(256) void conv_h_kernel(
    const float* __restrict__ src, __half* __restrict__ dst, int n4)
{
    int i = blockIdx.x * 256 + threadIdx.x;
    if (i >= n4) return;
    float4 v = ((const float4*)src)[i];
    ((uint32_t*)dst)[2 * i + 0] = packh2(v.x, v.y);
    ((uint32_t*)dst)[2 * i + 1] = packh2(v.z, v.w);
}

// all 4 weight matrices in one launch (grid.y selects matrix)
__global__ __launch_bounds__(256) void conv_w_kernel(
    const float* __restrict__ w0, const float* __restrict__ w1,
    const float* __restrict__ w2, const float* __restrict__ w3,
    __half* __restrict__ dst, int n4)
{
    int i = blockIdx.x * 256 + threadIdx.x;
    if (i >= n4) return;
    const int m = blockIdx.y;
    const float* src = (m == 0) ? w0 : (m == 1) ? w1 : (m == 2) ? w2 : w3;
    __half* d = dst + (size_t)m * CC * CC;
    float4 v = ((const float4*)src)[i];
    ((uint32_t*)d)[2 * i + 0] = packh2(v.x, v.y);
    ((uint32_t*)d)[2 * i + 1] = packh2(v.z, v.w);
}

// ================================================================================
// Fused QKV projection GEMM (1-term fp16): one launch for all three matrices.
// blockIdx.x in [0,24): mat = bx>>3, n-tile = bx&7. 128x128 tile/CTA, 8 warps,
// K-chunk 64, cp.async double-buffered. Output: fp16 single, scaled.
// ================================================================================
#define KC 64
#define NCHUNK (CC / KC)      // 16
#define TILE_B 16384          // 128 rows x 128B (64 fp16)
#define SMEM_QKV (2 * 2 * TILE_B)   // 65536

__global__ __launch_bounds__(256) void qkv_mma_kernel(
    const __half* __restrict__ xh, const __half* __restrict__ w,
    const float* __restrict__ bq, const float* __restrict__ bk,
    const float* __restrict__ bv,
    __half* __restrict__ qh, __half* __restrict__ kh, __half* __restrict__ vh)
{
    extern __shared__ char smem[];
    const uint32_t sbase = smem_u32(smem);
    const int tid = threadIdx.x;
    const int wid = tid >> 5;
    const int lane = tid & 31;
    const int wm = wid & 1;
    const int wn = wid >> 1;

    const int mat = blockIdx.x >> 3;
    const int bn = (blockIdx.x & 7) * 128;
    const int bm = blockIdx.y * 128;

    const __half* B = w + (size_t)mat * CC * CC;
    const float* bias = (mat == 0) ? bq : (mat == 1) ? bk : bv;
    __half* out = (mat == 0) ? qh : (mat == 1) ? kh : vh;
    const float scale = (mat == 0) ? 0.125f : 1.0f;

    const int lrow = (lane & 7) + ((lane >> 3) & 1) * 8;
    const int lkb = (lane >> 4) * 16;

    float acc[4][4][4];
#pragma unroll
    for (int a = 0; a < 4; a++)
#pragma unroll
        for (int b = 0; b < 4; b++)
#pragma unroll
            for (int c = 0; c < 4; c++) acc[a][b][c] = 0.0f;

    auto load_chunk = [&](int chunk, int buf) {
        const int k0 = chunk * KC;
        const uint32_t tbu = sbase + buf * 2 * TILE_B;
#pragma unroll
        for (int part = 0; part < 2; part++) {
            const __half* p = part ? B : xh;
            const int roff = part ? bn : bm;
            const uint32_t db = tbu + part * TILE_B;
#pragma unroll
            for (int f = tid; f < 1024; f += 256) {
                int row = f >> 3;
                int c16 = f & 7;
                cp16(db + SWZ(row, c16 * 16),
                     p + (size_t)(roff + row) * CC + k0 + c16 * 8);
            }
        }
        CP_COMMIT();
    };

    load_chunk(0, 0);

    for (int chunk = 0; chunk < NCHUNK; chunk++) {
        const int buf = chunk & 1;
        if (chunk + 1 < NCHUNK) {
            load_chunk(chunk + 1, buf ^ 1);
            CP_WAIT(1);
        } else {
            CP_WAIT(0);
        }
        __syncthreads();

        const uint32_t tA = sbase + buf * 2 * TILE_B;
        const uint32_t tB = tA + TILE_B;

#pragma unroll
        for (int ks = 0; ks < 4; ks++) {
            const int kb = ks * 32;
            uint32_t ah[4][4], bf[2][4];
#pragma unroll
            for (int mi = 0; mi < 4; mi++) {
                int row = wm * 64 + mi * 16 + lrow;
                ldm_x4(ah[mi], tA + SWZ(row, kb + lkb));
            }
#pragma unroll
            for (int nj2 = 0; nj2 < 2; nj2++) {
                int row = wn * 32 + nj2 * 16 + lrow;
                ldm_x4(bf[nj2], tB + SWZ(row, kb + lkb));
            }
#pragma unroll
            for (int mi = 0; mi < 4; mi++) {
#pragma unroll
                for (int nj = 0; nj < 4; nj++) {
                    const int h = nj & 1;
                    mma_f16(acc[mi][nj], ah[mi], bf[nj >> 1][h], bf[nj >> 1][h + 2]);
                }
            }
        }
        __syncthreads();
    }

    // epilogue: bias, scale, fp16 single out
    const int lr = lane >> 2;
    const int lc = (lane & 3) * 2;
#pragma unroll
    for (int nj = 0; nj < 4; nj++) {
        const int c = bn + wn * 32 + nj * 8 + lc;
        const float b0 = bias[c], b1 = bias[c + 1];
#pragma unroll
        for (int mi = 0; mi < 4; mi++) {
            const int r = bm + wm * 64 + mi * 16 + lr;
            float v0 = acc[mi][nj][0] + b0, v1 = acc[mi][nj][1] + b1;
            float v2 = acc[mi][nj][2] + b0, v3 = acc[mi][nj][3] + b1;
            *(uint32_t*)&out[(size_t)r * CC + c] = packh2(v0 * scale, v1 * scale);
            *(uint32_t*)&out[(size_t)(r + 8) * CC + c] = packh2(v2 * scale, v3 * scale);
        }
    }
}

// ================================================================================
// Output projection GEMM: 2-term fp16, (yh+yl) @ Wp^T -> fp32 out.
// ================================================================================
#define SMEM_PROJ (2 * 3 * TILE_B)  // 98304

__global__ __launch_bounds__(256) void proj_mma_kernel(
    const __half* __restrict__ Ah, const __half* __restrict__ Al,
    const __half* __restrict__ B, float* __restrict__ Cf)
{
    extern __shared__ char smem[];
    const uint32_t sbase = smem_u32(smem);
    const int tid = threadIdx.x;
    const int wid = tid >> 5;
    const int lane = tid & 31;
    const int wm = wid & 1;
    const int wn = wid >> 1;
    const int bm = blockIdx.y * 128;
    const int bn = blockIdx.x * 128;

    const __half* srcs[3] = {Ah, Al, B};

    const int lrow = (lane & 7) + ((lane >> 3) & 1) * 8;
    const int lkb = (lane >> 4) * 16;

    float acc[4][4][4];
#pragma unroll
    for (int a = 0; a < 4; a++)
#pragma unroll
        for (int b = 0; b < 4; b++)
#pragma unroll
            for (int c = 0; c < 4; c++) acc[a][b][c] = 0.0f;

    auto load_chunk = [&](int chunk, int buf) {
        const int k0 = chunk * KC;
        const uint32_t tbu = sbase + buf * 3 * TILE_B;
#pragma unroll
        for (int part = 0; part < 3; part++) {
            const __half* p = srcs[part];
            const int roff = (part < 2) ? bm : bn;
            const uint32_t db = tbu + part * TILE_B;
#pragma unroll
            for (int f = tid; f < 1024; f += 256) {
                int row = f >> 3;
                int c16 = f & 7;
                cp16(db + SWZ(row, c16 * 16),
                     p + (size_t)(roff + row) * CC + k0 + c16 * 8);
            }
        }
        CP_COMMIT();
    };

    load_chunk(0, 0);

    for (int chunk = 0; chunk < NCHUNK; chunk++) {
        const int buf = chunk & 1;
        if (chunk + 1 < NCHUNK) {
            load_chunk(chunk + 1, buf ^ 1);
            CP_WAIT(1);
        } else {
            CP_WAIT(0);
        }
        __syncthreads();

        const uint32_t tAh = sbase + buf * 3 * TILE_B;
        const uint32_t tAl = tAh + TILE_B;
        const uint32_t tB  = tAh + 2 * TILE_B;

#pragma unroll
        for (int ks = 0; ks < 4; ks++) {
            const int kb = ks * 32;
            uint32_t ah[4][4], al[4][4], bf[2][4];
#pragma unroll
            for (int mi = 0; mi < 4; mi++) {
                int row = wm * 64 + mi * 16 + lrow;
                uint32_t off = SWZ(row, kb + lkb);
                ldm_x4(ah[mi], tAh + off);
                ldm_x4(al[mi], tAl + off);
            }
#pragma unroll
            for (int nj2 = 0; nj2 < 2; nj2++) {
                int row = wn * 32 + nj2 * 16 + lrow;
                ldm_x4(bf[nj2], tB + SWZ(row, kb + lkb));
            }
#pragma unroll
            for (int mi = 0; mi < 4; mi++) {
#pragma unroll
                for (int nj = 0; nj < 4; nj++) {
                    const int h = nj & 1;
                    mma_f16(acc[mi][nj], ah[mi], bf[nj >> 1][h], bf[nj >> 1][h + 2]);
                    mma_f16(acc[mi][nj], al[mi], bf[nj >> 1][h], bf[nj >> 1][h + 2]);
                }
            }
        }
        __syncthreads();
    }

    const int lr = lane >> 2;
    const int lc = (lane & 3) * 2;
#pragma unroll
    for (int nj = 0; nj < 4; nj++) {
        const int c = bn + wn * 32 + nj * 8 + lc;
#pragma unroll
        for (int mi = 0; mi < 4; mi++) {
            const int r = bm + wm * 64 + mi * 16 + lr;
            *(float2*)&Cf[(size_t)r * CC + c] =
                make_float2(acc[mi][nj][0], acc[mi][nj][1]);
            *(float2*)&Cf[(size_t)(r + 8) * CC + c] =
                make_float2(acc[mi][nj][2], acc[mi][nj][3]);
        }
    }
}

// ================================================================================
// Flash attention via mma.sync, all-single fp16 operands (Q, K, V, P).
// CTA: 128 q-rows x one (b,h); heavy-first ordering (qt = 15 - blockIdx.x).
// KV tiles of 64, cp.async double-buffered. Causal tile-skip + diagonal mask.
// smem: Q 16KB + 2 x (K 8KB + V 8KB) = 48KB
// ================================================================================
#define ATT_SMEM 49152

__global__ __launch_bounds__(256) void attn_mma_kernel(
    const __half* __restrict__ qh, const __half* __restrict__ kh,
    const __half* __restrict__ vh,
    __half* __restrict__ yh, __half* __restrict__ yl)
{
    extern __shared__ char smem[];
    const uint32_t sb = smem_u32(smem);
    const uint32_t sQ = sb;
    const uint32_t sKV = sb + 16384;   // + buf*16384: K@0, V@8192

    const int tid = threadIdx.x;
    const int wid = tid >> 5;
    const int lane = tid & 31;
    const int lrow = (lane & 7) + ((lane >> 3) & 1) * 8;
    const int lkb = (lane >> 4) * 16;

    // heavy-first: largest qt launches earliest
    const int qt = (gridDim.x - 1) - blockIdx.x;
    const int q0 = qt * 128;
    const int bh = blockIdx.y;
    const int b = bh >> 4;
    const int h = bh & 15;
    const size_t base = (size_t)b * TT * CC + (size_t)h * HD;

    // Q tile load (single fp16): 128 rows x 128B
#pragma unroll
    for (int f = tid; f < 1024; f += 256) {
        int row = f >> 3, c16 = f & 7;
        cp16(sQ + SWZ(row, c16 * 16), qh + base + (size_t)(q0 + row) * CC + c16 * 8);
    }

    const __half* kvsrc[2] = {kh, vh};
    auto load_kv = [&](int kt, int buf) {
        const uint32_t db = sKV + buf * 16384;
#pragma unroll
        for (int f = tid; f < 1024; f += 256) {
            int mat = f >> 9, idx = f & 511;
            int row = idx >> 3, c16 = idx & 7;
            cp16(db + mat * 8192 + SWZ(row, c16 * 16),
                 kvsrc[mat] + base + (size_t)(kt * 64 + row) * CC + c16 * 8);
        }
    };

    const int nkt = 2 * (qt + 1);
    load_kv(0, 0);
    CP_COMMIT();

    float m0 = -3.0e38f, m1 = -3.0e38f, l0 = 0.0f, l1 = 0.0f;
    float o[8][4];
#pragma unroll
    for (int nt = 0; nt < 8; nt++)
#pragma unroll
        for (int c = 0; c < 4; c++) o[nt][c] = 0.0f;

    const int q0w = q0 + 16 * wid;

    for (int kt = 0; kt < nkt; kt++) {
        const int buf = kt & 1;
        if (kt + 1 < nkt) {
            load_kv(kt + 1, buf ^ 1);
            CP_COMMIT();
            CP_WAIT(1);
        } else {
            CP_WAIT(0);
        }
        __syncthreads();

        const int kc = kt * 64;
        if (kc <= q0w + 15) {   // not fully masked for this warp
            const uint32_t bK = sKV + buf * 16384;
            const uint32_t bV = bK + 8192;

            // ---- S = Q K^T (single fp16) ----
            float s[8][4];
#pragma unroll
            for (int nt = 0; nt < 8; nt++)
#pragma unroll
                for (int c = 0; c < 4; c++) s[nt][c] = 0.0f;

#pragma unroll
            for (int ks = 0; ks < 4; ks++) {
                const int kb = ks * 32;
                uint32_t a[4];
                ldm_x4(a, sQ + SWZ(16 * wid + lrow, kb + lkb));
#pragma unroll
                for (int nt2 = 0; nt2 < 4; nt2++) {
                    uint32_t bhf[4];
                    ldm_x4(bhf, bK + SWZ(nt2 * 16 + lrow, kb + lkb));
#pragma unroll
                    for (int hh = 0; hh < 2; hh++) {
                        mma_f16(s[nt2 * 2 + hh], a, bhf[hh], bhf[hh + 2]);
                    }
                }
            }

            // ---- causal mask on diagonal tiles ----
            if (kc + 63 > q0w) {
                const int r0 = q0w + (lane >> 2);
                const int r1 = r0 + 8;
#pragma unroll
                for (int nt = 0; nt < 8; nt++) {
                    int c0 = kc + 8 * nt + 2 * (lane & 3);
                    if (c0 > r0)     s[nt][0] = -1.0e30f;
                    if (c0 + 1 > r0) s[nt][1] = -1.0e30f;
                    if (c0 > r1)     s[nt][2] = -1.0e30f;
                    if (c0 + 1 > r1) s[nt][3] = -1.0e30f;
                }
            }

            // ---- online softmax ----
            float mt0 = -3.0e38f, mt1 = -3.0e38f;
#pragma unroll
            for (int nt = 0; nt < 8; nt++) {
                mt0 = fmaxf(mt0, fmaxf(s[nt][0], s[nt][1]));
                mt1 = fmaxf(mt1, fmaxf(s[nt][2], s[nt][3]));
            }
#pragma unroll
            for (int d = 1; d <= 2; d <<= 1) {
                mt0 = fmaxf(mt0, __shfl_xor_sync(0xffffffffu, mt0, d));
                mt1 = fmaxf(mt1, __shfl_xor_sync(0xffffffffu, mt1, d));
            }
            float mn0 = fmaxf(m0, mt0), mn1 = fmaxf(m1, mt1);
            float corr0 = __expf(m0 - mn0), corr1 = __expf(m1 - mn1);
            float ls0 = 0.0f, ls1 = 0.0f;
#pragma unroll
            for (int nt = 0; nt < 8; nt++) {
                s[nt][0] = __expf(s[nt][0] - mn0);
                s[nt][1] = __expf(s[nt][1] - mn0);
                s[nt][2] = __expf(s[nt][2] - mn1);
                s[nt][3] = __expf(s[nt][3] - mn1);
                ls0 += s[nt][0] + s[nt][1];
                ls1 += s[nt][2] + s[nt][3];
            }
#pragma unroll
            for (int d = 1; d <= 2; d <<= 1) {
                ls0 += __shfl_xor_sync(0xffffffffu, ls0, d);
                ls1 += __shfl_xor_sync(0xffffffffu, ls1, d);
            }
            l0 = l0 * corr0 + ls0;  m0 = mn0;
            l1 = l1 * corr1 + ls1;  m1 = mn1;
#pragma unroll
            for (int nt = 0; nt < 8; nt++) {
                o[nt][0] *= corr0; o[nt][1] *= corr0;
                o[nt][2] *= corr1; o[nt][3] *= corr1;
            }

            // ---- O += P V (single fp16) ----
#pragma unroll
            for (int ks = 0; ks < 4; ks++) {
                uint32_t a[4];
                a[0] = packh2(s[2 * ks][0], s[2 * ks][1]);
                a[1] = packh2(s[2 * ks][2], s[2 * ks][3]);
                a[2] = packh2(s[2 * ks + 1][0], s[2 * ks + 1][1]);
                a[3] = packh2(s[2 * ks + 1][2], s[2 * ks + 1][3]);
#pragma unroll
                for (int nt2 = 0; nt2 < 4; nt2++) {
                    uint32_t bvh[4];
                    ldm_x4_t(bvh, bV + SWZ(ks * 16 + lrow, nt2 * 32 + lkb));
#pragma unroll
                    for (int hh = 0; hh < 2; hh++) {
                        mma_f16(o[nt2 * 2 + hh], a, bvh[2 * hh], bvh[2 * hh + 1]);
                    }
                }
            }
        }
        __syncthreads();
    }

    // ---- normalize, split fp16 hi/lo, store ----
    const float inv0 = 1.0f / l0, inv1 = 1.0f / l1;
    const int t0 = q0w + (lane >> 2);
    const int t1 = t0 + 8;
#pragma unroll
    for (int nt = 0; nt < 8; nt++) {
        const int c = 8 * nt + 2 * (lane & 3);
        const size_t o0 = base + (size_t)t0 * CC + c;
        const size_t o1 = base + (size_t)t1 * CC + c;
        float v0 = o[nt][0] * inv0, v1 = o[nt][1] * inv0;
        float v2 = o[nt][2] * inv1, v3 = o[nt][3] * inv1;
        float r0, r1, r2, r3;
        uint32_t h01 = packh2_res(v0, v1, r0, r1);
        uint32_t h23 = packh2_res(v2, v3, r2, r3);
        *(uint32_t*)&yh[o0] = h01;
        *(uint32_t*)&yh[o1] = h23;
        *(uint32_t*)&yl[o0] = packh2(r0, r1);
        *(uint32_t*)&yl[o1] = packh2(r2, r3);
    }
}

// ================================================================================
// launch
// ================================================================================
extern "C" void kernel_launch(void* const* d_in, const int* in_sizes, int n_in,
                              void* d_out, int out_size)
{
    const float* x  = (const float*)d_in[0];
    const float* Wq = (const float*)d_in[1];
    const float* bq = (const float*)d_in[2];
    const float* Wk = (const float*)d_in[3];
    const float* bk = (const float*)d_in[4];
    const float* Wv = (const float*)d_in[5];
    const float* bv = (const float*)d_in[6];
    const float* Wp = (const float*)d_in[7];
    float* out = (float*)d_out;

    __half *xh, *qh, *kh, *vh, *yh, *yl, *w;
    cudaGetSymbolAddress((void**)&xh, g_xh);
    cudaGetSymbolAddress((void**)&qh, g_qh);
    cudaGetSymbolAddress((void**)&kh, g_kh);
    cudaGetSymbolAddress((void**)&vh, g_vh);
    cudaGetSymbolAddress((void**)&yh, g_yh);
    cudaGetSymbolAddress((void**)&yl, g_yl);
    cudaGetSymbolAddress((void**)&w,  g_w);

    const int WSZ = CC * CC;

    cudaFuncSetAttribute(qkv_mma_kernel, cudaFuncAttributeMaxDynamicSharedMemorySize,
                         SMEM_QKV);
    cudaFuncSetAttribute(proj_mma_kernel, cudaFuncAttributeMaxDynamicSharedMemorySize,
                         SMEM_PROJ);
    cudaFuncSetAttribute(attn_mma_kernel, cudaFuncAttributeMaxDynamicSharedMemorySize,
                         ATT_SMEM);

    // conversions: x (one launch) + all 4 weights (one launch)
    conv_h_kernel<<<ELEMS / 4 / 256, 256>>>(x, xh, ELEMS / 4);
    conv_w_kernel<<<dim3(WSZ / 4 / 256, 4), 256>>>(Wq, Wk, Wv, Wp, w, WSZ / 4);

    // fused QKV projections: 1-term fp16 (Q pre-scaled by 1/sqrt(HD))
    qkv_mma_kernel<<<dim3(24, MM / 128), 256, SMEM_QKV>>>(xh, w, bq, bk, bv,
                                                          qh, kh, vh);

    // attention (tensor-core fp16, heavy-first)
    attn_mma_kernel<<<dim3(TT / 128, BB * HH), 256, ATT_SMEM>>>(qh, kh, vh, yh, yl);

    // output projection: 2-term (yh+yl)·Wp -> fp32 out
    proj_mma_kernel<<<dim3(CC / 128, MM / 128), 256, SMEM_PROJ>>>(yh, yl,
                                                                  w + 3 * WSZ, out);
}

// round 9
// speedup vs baseline: 8.5105x; 1.1327x over previous
#include <cuda_runtime.h>
#include <cuda_bf16.h>
#include <cuda_fp16.h>
#include <cstdint>
#include <cstddef>

// Problem constants
#define BB 4
#define TT 2048
#define CC 1024
#define HH 16
#define HD 64
#define MM (BB * TT)          // 8192 rows

// ---------------- scratch (static device globals; no allocation) ----------------
#define ELEMS (BB * TT * CC)  // 8,388,608
__device__ __half g_xh[ELEMS];        // x: single fp16
__device__ __half g_qh[ELEMS];        // Q: single fp16 (pre-scaled)
__device__ __half g_kh[ELEMS];        // K: single fp16
__device__ __half g_vh[ELEMS];        // V: single fp16
__device__ __half g_yh[ELEMS];        // attention out (single fp16)
__device__ __half g_w[4 * CC * CC];   // weights: single fp16

// ================================================================================
// PTX helpers (base sm_103-safe: mma.sync / ldmatrix / cp.async only)
// ================================================================================
__device__ __forceinline__ uint32_t smem_u32(const void* p) {
    uint32_t a;
    asm("{ .reg .u64 t; cvta.to.shared.u64 t, %1; cvt.u32.u64 %0, t; }" : "=r"(a) : "l"(p));
    return a;
}

__device__ __forceinline__ void cp16(uint32_t dst, const void* src) {
    asm volatile("cp.async.cg.shared.global [%0], [%1], 16;" :: "r"(dst), "l"(src));
}
#define CP_COMMIT() asm volatile("cp.async.commit_group;" ::: "memory")
#define CP_WAIT(n)  asm volatile("cp.async.wait_group %0;" :: "n"(n) : "memory")

__device__ __forceinline__ void ldm_x4(uint32_t* r, uint32_t addr) {
    asm volatile("ldmatrix.sync.aligned.m8n8.x4.shared.b16 {%0,%1,%2,%3}, [%4];"
        : "=r"(r[0]), "=r"(r[1]), "=r"(r[2]), "=r"(r[3]) : "r"(addr));
}
__device__ __forceinline__ void ldm_x4_t(uint32_t* r, uint32_t addr) {
    asm volatile("ldmatrix.sync.aligned.m8n8.x4.trans.shared.b16 {%0,%1,%2,%3}, [%4];"
        : "=r"(r[0]), "=r"(r[1]), "=r"(r[2]), "=r"(r[3]) : "r"(addr));
}

__device__ __forceinline__ void mma_f16(float* d, const uint32_t* a,
                                        uint32_t b0, uint32_t b1) {
    asm volatile(
        "mma.sync.aligned.m16n8k16.row.col.f32.f16.f16.f32 "
        "{%0,%1,%2,%3}, {%4,%5,%6,%7}, {%8,%9}, {%0,%1,%2,%3};"
        : "+f"(d[0]), "+f"(d[1]), "+f"(d[2]), "+f"(d[3])
        : "r"(a[0]), "r"(a[1]), "r"(a[2]), "r"(a[3]), "r"(b0), "r"(b1));
}

// SW128 swizzle on a 128B-row tile
#define SWZ(row, kbyte) (((row) << 7) + ((kbyte) ^ (((row) & 7) << 4)))

// fp16 pack helpers
__device__ __forceinline__ uint32_t packh2(float x, float y) {
    __half2 p = __floats2half2_rn(x, y);
    return *reinterpret_cast<uint32_t*>(&p);
}

// ================================================================================
// fp32 -> fp16 single conversions
// ================================================================================
__global__ __launch_bounds__(256) void conv_h_kernel(
    const float* __restrict__ src, __half* __restrict__ dst, int n4)
{
    int i = blockIdx.x * 256 + threadIdx.x;
    if (i >= n4) return;
    float4 v = ((const float4*)src)[i];
    ((uint32_t*)dst)[2 * i + 0] = packh2(v.x, v.y);
    ((uint32_t*)dst)[2 * i + 1] = packh2(v.z, v.w);
}

// all 4 weight matrices in one launch (grid.y selects matrix)
__global__ __launch_bounds__(256) void conv_w_kernel(
    const float* __restrict__ w0, const float* __restrict__ w1,
    const float* __restrict__ w2, const float* __restrict__ w3,
    __half* __restrict__ dst, int n4)
{
    int i = blockIdx.x * 256 + threadIdx.x;
    if (i >= n4) return;
    const int m = blockIdx.y;
    const float* src = (m == 0) ? w0 : (m == 1) ? w1 : (m == 2) ? w2 : w3;
    __half* d = dst + (size_t)m * CC * CC;
    float4 v = ((const float4*)src)[i];
    ((uint32_t*)d)[2 * i + 0] = packh2(v.x, v.y);
    ((uint32_t*)d)[2 * i + 1] = packh2(v.z, v.w);
}

// ================================================================================
// Fused QKV projection GEMM (1-term fp16): one launch for all three matrices.
// blockIdx.x in [0,24): mat = bx>>3, n-tile = bx&7. 128x128 tile/CTA, 8 warps,
// K-chunk 64, cp.async double-buffered. Output: fp16 single, scaled.
// ================================================================================
#define KC 64
#define NCHUNK (CC / KC)      // 16
#define TILE_B 16384          // 128 rows x 128B (64 fp16)
#define SMEM_G (2 * 2 * TILE_B)   // 65536

__global__ __launch_bounds__(256) void qkv_mma_kernel(
    const __half* __restrict__ xh, const __half* __restrict__ w,
    const float* __restrict__ bq, const float* __restrict__ bk,
    const float* __restrict__ bv,
    __half* __restrict__ qh, __half* __restrict__ kh, __half* __restrict__ vh)
{
    extern __shared__ char smem[];
    const uint32_t sbase = smem_u32(smem);
    const int tid = threadIdx.x;
    const int wid = tid >> 5;
    const int lane = tid & 31;
    const int wm = wid & 1;
    const int wn = wid >> 1;

    const int mat = blockIdx.x >> 3;
    const int bn = (blockIdx.x & 7) * 128;
    const int bm = blockIdx.y * 128;

    const __half* B = w + (size_t)mat * CC * CC;
    const float* bias = (mat == 0) ? bq : (mat == 1) ? bk : bv;
    __half* out = (mat == 0) ? qh : (mat == 1) ? kh : vh;
    const float scale = (mat == 0) ? 0.125f : 1.0f;

    const int lrow = (lane & 7) + ((lane >> 3) & 1) * 8;
    const int lkb = (lane >> 4) * 16;

    float acc[4][4][4];
#pragma unroll
    for (int a = 0; a < 4; a++)
#pragma unroll
        for (int b = 0; b < 4; b++)
#pragma unroll
            for (int c = 0; c < 4; c++) acc[a][b][c] = 0.0f;

    auto load_chunk = [&](int chunk, int buf) {
        const int k0 = chunk * KC;
        const uint32_t tbu = sbase + buf * 2 * TILE_B;
#pragma unroll
        for (int part = 0; part < 2; part++) {
            const __half* p = part ? B : xh;
            const int roff = part ? bn : bm;
            const uint32_t db = tbu + part * TILE_B;
#pragma unroll
            for (int f = tid; f < 1024; f += 256) {
                int row = f >> 3;
                int c16 = f & 7;
                cp16(db + SWZ(row, c16 * 16),
                     p + (size_t)(roff + row) * CC + k0 + c16 * 8);
            }
        }
        CP_COMMIT();
    };

    load_chunk(0, 0);

    for (int chunk = 0; chunk < NCHUNK; chunk++) {
        const int buf = chunk & 1;
        if (chunk + 1 < NCHUNK) {
            load_chunk(chunk + 1, buf ^ 1);
            CP_WAIT(1);
        } else {
            CP_WAIT(0);
        }
        __syncthreads();

        const uint32_t tA = sbase + buf * 2 * TILE_B;
        const uint32_t tB = tA + TILE_B;

#pragma unroll
        for (int ks = 0; ks < 4; ks++) {
            const int kb = ks * 32;
            uint32_t ah[4][4], bf[2][4];
#pragma unroll
            for (int mi = 0; mi < 4; mi++) {
                int row = wm * 64 + mi * 16 + lrow;
                ldm_x4(ah[mi], tA + SWZ(row, kb + lkb));
            }
#pragma unroll
            for (int nj2 = 0; nj2 < 2; nj2++) {
                int row = wn * 32 + nj2 * 16 + lrow;
                ldm_x4(bf[nj2], tB + SWZ(row, kb + lkb));
            }
#pragma unroll
            for (int mi = 0; mi < 4; mi++) {
#pragma unroll
                for (int nj = 0; nj < 4; nj++) {
                    const int h = nj & 1;
                    mma_f16(acc[mi][nj], ah[mi], bf[nj >> 1][h], bf[nj >> 1][h + 2]);
                }
            }
        }
        __syncthreads();
    }

    // epilogue: bias, scale, fp16 single out
    const int lr = lane >> 2;
    const int lc = (lane & 3) * 2;
#pragma unroll
    for (int nj = 0; nj < 4; nj++) {
        const int c = bn + wn * 32 + nj * 8 + lc;
        const float b0 = bias[c], b1 = bias[c + 1];
#pragma unroll
        for (int mi = 0; mi < 4; mi++) {
            const int r = bm + wm * 64 + mi * 16 + lr;
            float v0 = acc[mi][nj][0] + b0, v1 = acc[mi][nj][1] + b1;
            float v2 = acc[mi][nj][2] + b0, v3 = acc[mi][nj][3] + b1;
            *(uint32_t*)&out[(size_t)r * CC + c] = packh2(v0 * scale, v1 * scale);
            *(uint32_t*)&out[(size_t)(r + 8) * CC + c] = packh2(v2 * scale, v3 * scale);
        }
    }
}

// ================================================================================
// Output projection GEMM: 1-term fp16, yh @ Wp^T -> fp32 out.
// ================================================================================
__global__ __launch_bounds__(256) void proj_mma_kernel(
    const __half* __restrict__ Ah, const __half* __restrict__ B,
    float* __restrict__ Cf)
{
    extern __shared__ char smem[];
    const uint32_t sbase = smem_u32(smem);
    const int tid = threadIdx.x;
    const int wid = tid >> 5;
    const int lane = tid & 31;
    const int wm = wid & 1;
    const int wn = wid >> 1;
    const int bm = blockIdx.y * 128;
    const int bn = blockIdx.x * 128;

    const int lrow = (lane & 7) + ((lane >> 3) & 1) * 8;
    const int lkb = (lane >> 4) * 16;

    float acc[4][4][4];
#pragma unroll
    for (int a = 0; a < 4; a++)
#pragma unroll
        for (int b = 0; b < 4; b++)
#pragma unroll
            for (int c = 0; c < 4; c++) acc[a][b][c] = 0.0f;

    auto load_chunk = [&](int chunk, int buf) {
        const int k0 = chunk * KC;
        const uint32_t tbu = sbase + buf * 2 * TILE_B;
#pragma unroll
        for (int part = 0; part < 2; part++) {
            const __half* p = part ? B : Ah;
            const int roff = part ? bn : bm;
            const uint32_t db = tbu + part * TILE_B;
#pragma unroll
            for (int f = tid; f < 1024; f += 256) {
                int row = f >> 3;
                int c16 = f & 7;
                cp16(db + SWZ(row, c16 * 16),
                     p + (size_t)(roff + row) * CC + k0 + c16 * 8);
            }
        }
        CP_COMMIT();
    };

    load_chunk(0, 0);

    for (int chunk = 0; chunk < NCHUNK; chunk++) {
        const int buf = chunk & 1;
        if (chunk + 1 < NCHUNK) {
            load_chunk(chunk + 1, buf ^ 1);
            CP_WAIT(1);
        } else {
            CP_WAIT(0);
        }
        __syncthreads();

        const uint32_t tA = sbase + buf * 2 * TILE_B;
        const uint32_t tB = tA + TILE_B;

#pragma unroll
        for (int ks = 0; ks < 4; ks++) {
            const int kb = ks * 32;
            uint32_t ah[4][4], bf[2][4];
#pragma unroll
            for (int mi = 0; mi < 4; mi++) {
                int row = wm * 64 + mi * 16 + lrow;
                ldm_x4(ah[mi], tA + SWZ(row, kb + lkb));
            }
#pragma unroll
            for (int nj2 = 0; nj2 < 2; nj2++) {
                int row = wn * 32 + nj2 * 16 + lrow;
                ldm_x4(bf[nj2], tB + SWZ(row, kb + lkb));
            }
#pragma unroll
            for (int mi = 0; mi < 4; mi++) {
#pragma unroll
                for (int nj = 0; nj < 4; nj++) {
                    const int h = nj & 1;
                    mma_f16(acc[mi][nj], ah[mi], bf[nj >> 1][h], bf[nj >> 1][h + 2]);
                }
            }
        }
        __syncthreads();
    }

    const int lr = lane >> 2;
    const int lc = (lane & 3) * 2;
#pragma unroll
    for (int nj = 0; nj < 4; nj++) {
        const int c = bn + wn * 32 + nj * 8 + lc;
#pragma unroll
        for (int mi = 0; mi < 4; mi++) {
            const int r = bm + wm * 64 + mi * 16 + lr;
            *(float2*)&Cf[(size_t)r * CC + c] =
                make_float2(acc[mi][nj][0], acc[mi][nj][1]);
            *(float2*)&Cf[(size_t)(r + 8) * CC + c] =
                make_float2(acc[mi][nj][2], acc[mi][nj][3]);
        }
    }
}

// ================================================================================
// Flash attention via mma.sync, all-single fp16 operands (Q, K, V, P).
// CTA: 128 q-rows x one (b,h); heavy-first ordering (qt = 15 - blockIdx.x).
// KV tiles of 64, cp.async double-buffered. Causal tile-skip + diagonal mask.
// smem: Q 16KB + 2 x (K 8KB + V 8KB) = 48KB. Output: single fp16.
// ================================================================================
#define ATT_SMEM 49152

__global__ __launch_bounds__(256) void attn_mma_kernel(
    const __half* __restrict__ qh, const __half* __restrict__ kh,
    const __half* __restrict__ vh, __half* __restrict__ yh)
{
    extern __shared__ char smem[];
    const uint32_t sb = smem_u32(smem);
    const uint32_t sQ = sb;
    const uint32_t sKV = sb + 16384;   // + buf*16384: K@0, V@8192

    const int tid = threadIdx.x;
    const int wid = tid >> 5;
    const int lane = tid & 31;
    const int lrow = (lane & 7) + ((lane >> 3) & 1) * 8;
    const int lkb = (lane >> 4) * 16;

    // heavy-first: largest qt launches earliest
    const int qt = (gridDim.x - 1) - blockIdx.x;
    const int q0 = qt * 128;
    const int bh = blockIdx.y;
    const int b = bh >> 4;
    const int h = bh & 15;
    const size_t base = (size_t)b * TT * CC + (size_t)h * HD;

    // Q tile load (single fp16): 128 rows x 128B
#pragma unroll
    for (int f = tid; f < 1024; f += 256) {
        int row = f >> 3, c16 = f & 7;
        cp16(sQ + SWZ(row, c16 * 16), qh + base + (size_t)(q0 + row) * CC + c16 * 8);
    }

    const __half* kvsrc[2] = {kh, vh};
    auto load_kv = [&](int kt, int buf) {
        const uint32_t db = sKV + buf * 16384;
#pragma unroll
        for (int f = tid; f < 1024; f += 256) {
            int mat = f >> 9, idx = f & 511;
            int row = idx >> 3, c16 = idx & 7;
            cp16(db + mat * 8192 + SWZ(row, c16 * 16),
                 kvsrc[mat] + base + (size_t)(kt * 64 + row) * CC + c16 * 8);
        }
    };

    const int nkt = 2 * (qt + 1);
    load_kv(0, 0);
    CP_COMMIT();

    float m0 = -3.0e38f, m1 = -3.0e38f, l0 = 0.0f, l1 = 0.0f;
    float o[8][4];
#pragma unroll
    for (int nt = 0; nt < 8; nt++)
#pragma unroll
        for (int c = 0; c < 4; c++) o[nt][c] = 0.0f;

    const int q0w = q0 + 16 * wid;

    for (int kt = 0; kt < nkt; kt++) {
        const int buf = kt & 1;
        if (kt + 1 < nkt) {
            load_kv(kt + 1, buf ^ 1);
            CP_COMMIT();
            CP_WAIT(1);
        } else {
            CP_WAIT(0);
        }
        __syncthreads();

        const int kc = kt * 64;
        if (kc <= q0w + 15) {   // not fully masked for this warp
            const uint32_t bK = sKV + buf * 16384;
            const uint32_t bV = bK + 8192;

            // ---- S = Q K^T (single fp16) ----
            float s[8][4];
#pragma unroll
            for (int nt = 0; nt < 8; nt++)
#pragma unroll
                for (int c = 0; c < 4; c++) s[nt][c] = 0.0f;

#pragma unroll
            for (int ks = 0; ks < 4; ks++) {
                const int kb = ks * 32;
                uint32_t a[4];
                ldm_x4(a, sQ + SWZ(16 * wid + lrow, kb + lkb));
#pragma unroll
                for (int nt2 = 0; nt2 < 4; nt2++) {
                    uint32_t bhf[4];
                    ldm_x4(bhf, bK + SWZ(nt2 * 16 + lrow, kb + lkb));
#pragma unroll
                    for (int hh = 0; hh < 2; hh++) {
                        mma_f16(s[nt2 * 2 + hh], a, bhf[hh], bhf[hh + 2]);
                    }
                }
            }

            // ---- causal mask on diagonal tiles ----
            if (kc + 63 > q0w) {
                const int r0 = q0w + (lane >> 2);
                const int r1 = r0 + 8;
#pragma unroll
                for (int nt = 0; nt < 8; nt++) {
                    int c0 = kc + 8 * nt + 2 * (lane & 3);
                    if (c0 > r0)     s[nt][0] = -1.0e30f;
                    if (c0 + 1 > r0) s[nt][1] = -1.0e30f;
                    if (c0 > r1)     s[nt][2] = -1.0e30f;
                    if (c0 + 1 > r1) s[nt][3] = -1.0e30f;
                }
            }

            // ---- online softmax ----
            float mt0 = -3.0e38f, mt1 = -3.0e38f;
#pragma unroll
            for (int nt = 0; nt < 8; nt++) {
                mt0 = fmaxf(mt0, fmaxf(s[nt][0], s[nt][1]));
                mt1 = fmaxf(mt1, fmaxf(s[nt][2], s[nt][3]));
            }
#pragma unroll
            for (int d = 1; d <= 2; d <<= 1) {
                mt0 = fmaxf(mt0, __shfl_xor_sync(0xffffffffu, mt0, d));
                mt1 = fmaxf(mt1, __shfl_xor_sync(0xffffffffu, mt1, d));
            }
            float mn0 = fmaxf(m0, mt0), mn1 = fmaxf(m1, mt1);
            float corr0 = __expf(m0 - mn0), corr1 = __expf(m1 - mn1);
            float ls0 = 0.0f, ls1 = 0.0f;
#pragma unroll
            for (int nt = 0; nt < 8; nt++) {
                s[nt][0] = __expf(s[nt][0] - mn0);
                s[nt][1] = __expf(s[nt][1] - mn0);
                s[nt][2] = __expf(s[nt][2] - mn1);
                s[nt][3] = __expf(s[nt][3] - mn1);
                ls0 += s[nt][0] + s[nt][1];
                ls1 += s[nt][2] + s[nt][3];
            }
#pragma unroll
            for (int d = 1; d <= 2; d <<= 1) {
                ls0 += __shfl_xor_sync(0xffffffffu, ls0, d);
                ls1 += __shfl_xor_sync(0xffffffffu, ls1, d);
            }
            l0 = l0 * corr0 + ls0;  m0 = mn0;
            l1 = l1 * corr1 + ls1;  m1 = mn1;
#pragma unroll
            for (int nt = 0; nt < 8; nt++) {
                o[nt][0] *= corr0; o[nt][1] *= corr0;
                o[nt][2] *= corr1; o[nt][3] *= corr1;
            }

            // ---- O += P V (single fp16) ----
#pragma unroll
            for (int ks = 0; ks < 4; ks++) {
                uint32_t a[4];
                a[0] = packh2(s[2 * ks][0], s[2 * ks][1]);
                a[1] = packh2(s[2 * ks][2], s[2 * ks][3]);
                a[2] = packh2(s[2 * ks + 1][0], s[2 * ks + 1][1]);
                a[3] = packh2(s[2 * ks + 1][2], s[2 * ks + 1][3]);
#pragma unroll
                for (int nt2 = 0; nt2 < 4; nt2++) {
                    uint32_t bvh[4];
                    ldm_x4_t(bvh, bV + SWZ(ks * 16 + lrow, nt2 * 32 + lkb));
#pragma unroll
                    for (int hh = 0; hh < 2; hh++) {
                        mma_f16(o[nt2 * 2 + hh], a, bvh[2 * hh], bvh[2 * hh + 1]);
                    }
                }
            }
        }
        __syncthreads();
    }

    // ---- normalize, store single fp16 ----
    const float inv0 = 1.0f / l0, inv1 = 1.0f / l1;
    const int t0 = q0w + (lane >> 2);
    const int t1 = t0 + 8;
#pragma unroll
    for (int nt = 0; nt < 8; nt++) {
        const int c = 8 * nt + 2 * (lane & 3);
        *(uint32_t*)&yh[base + (size_t)t0 * CC + c] =
            packh2(o[nt][0] * inv0, o[nt][1] * inv0);
        *(uint32_t*)&yh[base + (size_t)t1 * CC + c] =
            packh2(o[nt][2] * inv1, o[nt][3] * inv1);
    }
}

// ================================================================================
// launch
// ================================================================================
extern "C" void kernel_launch(void* const* d_in, const int* in_sizes, int n_in,
                              void* d_out, int out_size)
{
    const float* x  = (const float*)d_in[0];
    const float* Wq = (const float*)d_in[1];
    const float* bq = (const float*)d_in[2];
    const float* Wk = (const float*)d_in[3];
    const float* bk = (const float*)d_in[4];
    const float* Wv = (const float*)d_in[5];
    const float* bv = (const float*)d_in[6];
    const float* Wp = (const float*)d_in[7];
    float* out = (float*)d_out;

    __half *xh, *qh, *kh, *vh, *yh, *w;
    cudaGetSymbolAddress((void**)&xh, g_xh);
    cudaGetSymbolAddress((void**)&qh, g_qh);
    cudaGetSymbolAddress((void**)&kh, g_kh);
    cudaGetSymbolAddress((void**)&vh, g_vh);
    cudaGetSymbolAddress((void**)&yh, g_yh);
    cudaGetSymbolAddress((void**)&w,  g_w);

    const int WSZ = CC * CC;

    cudaFuncSetAttribute(qkv_mma_kernel, cudaFuncAttributeMaxDynamicSharedMemorySize,
                         SMEM_G);
    cudaFuncSetAttribute(proj_mma_kernel, cudaFuncAttributeMaxDynamicSharedMemorySize,
                         SMEM_G);
    cudaFuncSetAttribute(attn_mma_kernel, cudaFuncAttributeMaxDynamicSharedMemorySize,
                         ATT_SMEM);

    // conversions: x (one launch) + all 4 weights (one launch)
    conv_h_kernel<<<ELEMS / 4 / 256, 256>>>(x, xh, ELEMS / 4);
    conv_w_kernel<<<dim3(WSZ / 4 / 256, 4), 256>>>(Wq, Wk, Wv, Wp, w, WSZ / 4);

    // fused QKV projections: 1-term fp16 (Q pre-scaled by 1/sqrt(HD))
    qkv_mma_kernel<<<dim3(24, MM / 128), 256, SMEM_G>>>(xh, w, bq, bk, bv,
                                                        qh, kh, vh);

    // attention (tensor-core fp16, heavy-first, single-fp16 out)
    attn_mma_kernel<<<dim3(TT / 128, BB * HH), 256, ATT_SMEM>>>(qh, kh, vh, yh);

    // output projection: 1-term yh·Wp -> fp32 out
    proj_mma_kernel<<<dim3(CC / 128, MM / 128), 256, SMEM_G>>>(yh, w + 3 * WSZ, out);
}